// round 5
// baseline (speedup 1.0000x reference)
#include <cuda_runtime.h>
#include <math.h>

// ---------------- problem constants ----------------
#define CB   32
#define CN   379
#define CH   512
#define CNH  8
#define CP   3
#define CWGH 4
#define CHD  64          // CH/CNH
#define CBN  (CB*CN)     // 12128
#define CBPN (CB*CP*CN)  // 36384
#define CNN  (CN*CN)     // 143641

#define X_SZ   (CBN*CH)          // 6209536
#define LOSS_OFF (2*X_SZ)
#define AWFC_OFF (LOSS_OFF+1)
#define AWSC_OFF (AWFC_OFF + CB*CP)

// ---------------- static scratch (zero-init by default) ----------------
static __device__ float g_z[CBN*CH];
static __device__ float g_qkv[CBN*3*CH];
static __device__ float g_pe[(long long)CBPN*CH];
static __device__ float g_h[(long long)CBPN*CH];
static __device__ float g_zc[CBN*CH];
static __device__ float g_fn[CBN*CH];
static __device__ float g_mask[(long long)CB*CNN];
static __device__ float g_scores[(long long)CB*CNH*CNN];
static __device__ float g_ctx[CBN*CH];
static __device__ float g_attnout[CBN*CH];
static __device__ float g_ffnh[(long long)CBN*4*CH];
static __device__ float g_ffnout[CBN*CH];
static __device__ float g_proj0[CBN*CH];
static __device__ float g_proj1[CBN*CH];
static __device__ float g_gbar[CB*CP*CH];
static __device__ float g_tokens[CB*CP*CH];
static __device__ float g_qkvwg[CB*CP*3*CH];
static __device__ float g_dot[CB*CP], g_psq[CB*CP], g_pabs[CB*CP], g_csq[CB];
static __device__ float g_sw[CB*CP], g_invmass[CB*CP], g_msum[CB];
static __device__ double g_kl[2];

// ---------------- fp32 GEMM, 1-D grid: C = act(A@W + bias + res) ----------------
// A:(M,K) row-major, W:(K,Nc) row-major. 64x64 tile, 256 threads, k-chunk 8.
// block index linearized: bx = blockIdx.x % gridNx, by = blockIdx.x / gridNx.
// resMode: 0 none, 1 res[gm*Nc+gn], 2 res[(b*CN+n)*Nc+gn] with gm=(b*CP+p)*CN+n.
__global__ void gemm3(const float* __restrict__ A, const float* __restrict__ W,
                      const float* __restrict__ bias, float* __restrict__ C,
                      int M, int K, int Nc, int gridNx,
                      const float* __restrict__ rowScale, int rowScaleDiv,
                      const float* __restrict__ res, int resMode, int act)
{
    __shared__ float As[64][9];   // [m][k]
    __shared__ float Ws[8][68];   // [k][n]
    const int t  = threadIdx.x;              // 0..255
    const int bx = blockIdx.x % gridNx;
    const int by = blockIdx.x / gridNx;
    const int m0 = by * 64;
    const int n0 = bx * 64;
    const int am = t >> 2;                   // 0..63
    const int ak = (t & 3) * 2;              // 0,2,4,6
    const int wk = t >> 5;                   // 0..7
    const int wn = (t & 31) * 2;             // 0..62
    const int tm = (t >> 4) * 4;             // 0..60
    const int tn = (t & 15) * 4;             // 0..60

    const int gmA = m0 + am;
    float sc = 1.f;
    if (rowScale && gmA < M) sc = rowScale[gmA / rowScaleDiv];

    float acc[4][4] = {};
    for (int kk = 0; kk < K; kk += 8) {
        #pragma unroll
        for (int u = 0; u < 2; u++) {
            int gk = kk + ak + u;
            As[am][ak + u] = (gmA < M && gk < K) ? A[(long long)gmA * K + gk] * sc : 0.f;
        }
        {
            int gk = kk + wk;
            #pragma unroll
            for (int u = 0; u < 2; u++) {
                int gn = n0 + wn + u;
                Ws[wk][wn + u] = (gk < K && gn < Nc) ? W[(long long)gk * Nc + gn] : 0.f;
            }
        }
        __syncthreads();
        #pragma unroll
        for (int k = 0; k < 8; k++) {
            float a[4], b[4];
            #pragma unroll
            for (int i = 0; i < 4; i++) a[i] = As[tm + i][k];
            #pragma unroll
            for (int j = 0; j < 4; j++) b[j] = Ws[k][tn + j];
            #pragma unroll
            for (int i = 0; i < 4; i++)
                #pragma unroll
                for (int j = 0; j < 4; j++)
                    acc[i][j] += a[i] * b[j];
        }
        __syncthreads();
    }

    #pragma unroll
    for (int i = 0; i < 4; i++) {
        int gm = m0 + tm + i;
        if (gm >= M) continue;
        long long resBase = 0;
        if (resMode == 1) resBase = (long long)gm * Nc;
        else if (resMode == 2) {
            int bb = gm / (CP * CN);
            int nn = gm % CN;
            resBase = ((long long)bb * CN + nn) * (long long)Nc;
        }
        #pragma unroll
        for (int j = 0; j < 4; j++) {
            int gn = n0 + tn + j;
            if (gn >= Nc) continue;
            float v = acc[i][j];
            if (bias) v += bias[gn];
            if (resMode) v += res[resBase + gn];
            if (act) v = 0.5f * v * (1.f + erff(v * 0.70710678118654752f));
            C[(long long)gm * Nc + gn] = v;
        }
    }
}

// ---------------- layernorm: one block per row, CH=512, 256 threads ----------------
__global__ void k_layernorm(const float* __restrict__ x, const float* __restrict__ g,
                            const float* __restrict__ b, float* __restrict__ z)
{
    int row = blockIdx.x;
    const float* xr = x + (long long)row*CH;
    float* zr = z + (long long)row*CH;
    __shared__ float red[256];
    int t = threadIdx.x;
    float v0 = xr[t], v1 = xr[t+256];
    red[t] = v0+v1; __syncthreads();
    for (int o=128;o>0;o>>=1){ if(t<o) red[t]+=red[t+o]; __syncthreads(); }
    float mean = red[0]*(1.f/CH); __syncthreads();
    float d0=v0-mean, d1=v1-mean;
    red[t]=d0*d0+d1*d1; __syncthreads();
    for (int o=128;o>0;o>>=1){ if(t<o) red[t]+=red[t+o]; __syncthreads(); }
    float rstd = rsqrtf(red[0]*(1.f/CH) + 1e-5f);
    zr[t]     = d0*rstd*g[t]     + b[t];
    zr[t+256] = d1*rstd*g[t+256] + b[t+256];
}

// ---------------- prior reductions ----------------
__global__ void k_prior_reduce(const float* __restrict__ pri, const float* __restrict__ conn)
{
    int bp = blockIdx.x; int b = bp / CP;
    const float* p = pri + (long long)bp*CNN;
    const float* c = conn + (long long)b*CNN;
    float dot=0, sq=0, ab=0;
    for (int i = threadIdx.x; i < CNN; i += blockDim.x) {
        float pv = p[i];
        dot += pv*c[i]; sq += pv*pv; ab += fabsf(pv);
    }
    __shared__ float r1[256], r2[256], r3[256];
    int t=threadIdx.x; r1[t]=dot;r2[t]=sq;r3[t]=ab; __syncthreads();
    for(int o=128;o>0;o>>=1){ if(t<o){r1[t]+=r1[t+o];r2[t]+=r2[t+o];r3[t]+=r3[t+o];} __syncthreads(); }
    if(t==0){ g_dot[bp]=r1[0]; g_psq[bp]=r2[0]; g_pabs[bp]=r3[0]; }
}

__global__ void k_conn_sumsq(const float* __restrict__ conn)
{
    int b = blockIdx.x;
    const float* c = conn + (long long)b*CNN;
    float sq=0;
    for (int i = threadIdx.x; i < CNN; i += blockDim.x) { float v=c[i]; sq += v*v; }
    __shared__ float r[256];
    int t=threadIdx.x; r[t]=sq; __syncthreads();
    for(int o=128;o>0;o>>=1){ if(t<o) r[t]+=r[t+o]; __syncthreads(); }
    if(t==0) g_csq[b]=r[0];
}

__global__ void k_sw()
{
    if (threadIdx.x) return;
    int b = blockIdx.x;
    float cn = fmaxf(sqrtf(g_csq[b]), 1e-12f);
    float s[CP], mx=-1e30f;
    for (int p=0;p<CP;p++){
        float pn = fmaxf(sqrtf(g_psq[b*CP+p]), 1e-12f);
        s[p] = g_dot[b*CP+p]/(cn*pn);
        mx = fmaxf(mx, s[p]);
    }
    float sum=0;
    for (int p=0;p<CP;p++){ s[p]=expf(s[p]-mx); sum+=s[p]; }
    for (int p=0;p<CP;p++){
        g_sw[b*CP+p]=s[p]/sum;
        g_invmass[b*CP+p] = 1.f/g_pabs[b*CP+p];
    }
}

// ---------------- fused_nh[b,n,c] = sum_p sw[b,p]*pe[b,p,n,c] ----------------
__global__ void k_fused_nh()
{
    long long idx = (long long)blockIdx.x*blockDim.x + threadIdx.x;
    if (idx >= (long long)CBN*CH) return;
    int c = (int)(idx % CH);
    long long bn = idx / CH;
    int b = (int)(bn / CN), n = (int)(bn % CN);
    float acc=0;
    #pragma unroll
    for (int p=0;p<CP;p++)
        acc += g_sw[b*CP+p]*g_pe[((long long)(b*CP+p)*CN + n)*CH + c];
    g_fn[idx]=acc;
}

// ---------------- gbar = mean_n gelu-out (g_h), 256 threads ----------------
__global__ void k_gbar()
{
    int bp = blockIdx.x; int c = threadIdx.x;
    float a0=0, a1=0;
    for (int n=0;n<CN;n++){
        const float* r = g_h + ((long long)bp*CN+n)*CH;
        a0 += r[c]; a1 += r[c+256];
    }
    g_gbar[bp*CH+c]     = a0*(1.f/CN);
    g_gbar[bp*CH+c+256] = a1*(1.f/CN);
}

// ---------------- tiny weight-gen MHA -> aw_, msum ----------------
__global__ void k_wg_attn(float* __restrict__ aw_out)
{
    int b = blockIdx.x;
    __shared__ float logit[CWGH*CP*CP];   // 36 floats
    int t = threadIdx.x;                  // 64 threads
    if (t < CWGH*CP*CP) {
        int h = t/(CP*CP); int i = (t/CP)%CP; int j = t%CP;
        const float* q = g_qkvwg + (long long)(b*CP+i)*3*CH + h*128;
        const float* k = g_qkvwg + (long long)(b*CP+j)*3*CH + CH + h*128;
        float d=0;
        for (int x=0;x<128;x++) d += q[x]*k[x];
        logit[t] = d*0.08838834764831845f;   // 1/sqrt(128)
    }
    __syncthreads();
    if (t==0) {
        float aw[CP]={0,0,0};
        for (int h=0;h<CWGH;h++) for (int i=0;i<CP;i++) {
            float mx=-1e30f;
            for (int j=0;j<CP;j++) mx=fmaxf(mx, logit[(h*CP+i)*CP+j]);
            float e[CP], s=0;
            for (int j=0;j<CP;j++){ e[j]=expf(logit[(h*CP+i)*CP+j]-mx); s+=e[j]; }
            for (int j=0;j<CP;j++) aw[j]+= e[j]/s;
        }
        for (int j=0;j<CP;j++) aw[j] *= (1.f/(CWGH*CP));
        float mx=-1e30f;
        for (int j=0;j<CP;j++) mx=fmaxf(mx, aw[j]);
        float s=0, e[CP];
        for (int j=0;j<CP;j++){ e[j]=expf((aw[j]-mx)*100.f); s+=e[j]; }  // temp 0.01
        float msum=0;
        for (int j=0;j<CP;j++){ float a=e[j]/s; aw_out[b*CP+j]=a; msum+=a; }
        g_msum[b]=msum;
    }
}

// ---------------- mask = tanh(a/2*msum + (1-a/2)*conn) ----------------
__global__ void k_mask(const float* __restrict__ conn, const float* __restrict__ alpha)
{
    long long idx = (long long)blockIdx.x*blockDim.x + threadIdx.x;
    if (idx >= (long long)CB*CNN) return;
    int b = (int)(idx / CNN);
    float a2 = alpha[0]*0.5f;
    g_mask[idx] = tanhf(a2*g_msum[b] + (1.f-a2)*conn[idx]);
}

// ---------------- scores: 1-D grid, 256 thr, 32x32 tile, k-chunk 16 ----------------
__global__ void k_scores()
{
    int blk = blockIdx.x;            // 256*144 blocks
    int bh = blk / 144;
    int r  = blk % 144;
    int b = bh >> 3, h = bh & 7;
    int i0 = (r / 12) * 32, j0 = (r % 12) * 32;
    __shared__ float Qs[32][17], Ks[32][17];
    int t = threadIdx.x;
    int lr = t >> 3;                 // 0..31
    int lc = (t & 7) * 2;            // 0..14
    int ti = t >> 4, tj = t & 15;
    float a00=0,a01=0,a10=0,a11=0;
    int gi_l = i0 + lr, gj_l = j0 + lr;
    for (int k0 = 0; k0 < CHD; k0 += 16) {
        #pragma unroll
        for (int u=0;u<2;u++){
            Qs[lr][lc+u] = (gi_l<CN)? g_qkv[(long long)(b*CN+gi_l)*3*CH + h*CHD + k0+lc+u] : 0.f;
            Ks[lr][lc+u] = (gj_l<CN)? g_qkv[(long long)(b*CN+gj_l)*3*CH + CH + h*CHD + k0+lc+u] : 0.f;
        }
        __syncthreads();
        #pragma unroll
        for (int x=0;x<16;x++){
            float q0=Qs[ti][x], q1=Qs[ti+16][x];
            float kv0=Ks[tj][x], kv1=Ks[tj+16][x];
            a00+=q0*kv0; a01+=q0*kv1; a10+=q1*kv0; a11+=q1*kv1;
        }
        __syncthreads();
    }
    float* srow = g_scores + (long long)bh*CNN;
    const float* mrow = g_mask + (long long)b*CNN;
    int i_[2] = {i0+ti, i0+ti+16};
    int j_[2] = {j0+tj, j0+tj+16};
    float av[2][2] = {{a00,a01},{a10,a11}};
    #pragma unroll
    for (int ii=0;ii<2;ii++){
        if (i_[ii] >= CN) continue;
        #pragma unroll
        for (int jj=0;jj<2;jj++){
            if (j_[jj] >= CN) continue;
            long long o = (long long)i_[ii]*CN + j_[jj];
            srow[o] = 0.125f*av[ii][jj]*(1.f + mrow[o]);
        }
    }
}

__global__ void k_softmax_rows(float* __restrict__ s, int cols)
{
    long long row = blockIdx.x;
    float* r = s + row*(long long)cols;
    __shared__ float red[128];
    int t = threadIdx.x;
    float mx = -1e30f;
    for (int c=t;c<cols;c+=128) mx = fmaxf(mx, r[c]);
    red[t]=mx; __syncthreads();
    for(int o=64;o>0;o>>=1){ if(t<o) red[t]=fmaxf(red[t],red[t+o]); __syncthreads(); }
    mx = red[0]; __syncthreads();
    float sum=0;
    for (int c=t;c<cols;c+=128){ float e=expf(r[c]-mx); r[c]=e; sum+=e; }
    red[t]=sum; __syncthreads();
    for(int o=64;o>0;o>>=1){ if(t<o) red[t]+=red[t+o]; __syncthreads(); }
    float inv = 1.f/red[0];
    for (int c=t;c<cols;c+=128) r[c]*=inv;
}

// ---------------- ctx = P @ V, 1-D grid, 256 thr, j-chunk 16 ----------------
__global__ void k_ctx()
{
    int blk = blockIdx.x;            // 32*8*12 = 3072 blocks
    int b = blk / 96;
    int rem = blk % 96;
    int h = rem / 12;
    int i0 = (rem % 12) * 32;
    int t = threadIdx.x;
    int tx = t & 63;                 // d
    int ty = t >> 6;                 // 0..3
    __shared__ float Ps[32][17], Vs[16][65];
    float acc[8]={};
    const float* srow = g_scores + (long long)(b*CNH+h)*CNN;
    int pr = t >> 3, pc = (t & 7) * 2;   // Ps loader
    int vr = t >> 4, vc = (t & 15) * 4;  // Vs loader
    for (int j0=0;j0<CN;j0+=16) {
        int gi = i0 + pr;
        #pragma unroll
        for (int u=0;u<2;u++){
            int gj = j0 + pc + u;
            Ps[pr][pc+u] = (gi<CN && gj<CN) ? srow[(long long)gi*CN+gj] : 0.f;
        }
        int gj = j0 + vr;
        #pragma unroll
        for (int u=0;u<4;u++)
            Vs[vr][vc+u] = (gj<CN) ? g_qkv[(long long)(b*CN+gj)*3*CH + 2*CH + h*CHD + vc+u] : 0.f;
        __syncthreads();
        #pragma unroll
        for (int jj=0;jj<16;jj++){
            float vv = Vs[jj][tx];
            #pragma unroll
            for (int ii=0;ii<8;ii++)
                acc[ii] += Ps[ty+4*ii][jj]*vv;
        }
        __syncthreads();
    }
    #pragma unroll
    for (int ii=0;ii<8;ii++){
        int gi = i0+ty+4*ii;
        if (gi<CN) g_ctx[(long long)(b*CN+gi)*CH + h*CHD + tx] = acc[ii];
    }
}

// ---------------- elementwise combines ----------------
__global__ void k_add3(const float* __restrict__ x)
{
    long long idx = (long long)blockIdx.x*blockDim.x + threadIdx.x;
    if (idx >= (long long)CBN*CH) return;
    g_attnout[idx] = x[idx] + g_ctx[idx] + g_fn[idx];
}

__global__ void k_final(float* __restrict__ outx, const float* __restrict__ dwp, int sidx)
{
    long long idx = (long long)blockIdx.x*blockDim.x + threadIdx.x;
    if (idx >= (long long)CBN*CH) return;
    float w = dwp[sidx];
    float f = g_ffnout[idx];
    float xn = g_attnout[idx] + f;
    outx[idx] = xn;
    float pv = w*f + (1.f-w)*xn;
    if (sidx == 0) g_proj0[idx] = pv; else g_proj1[idx] = pv;
}

__global__ void k_logsoftmax(int which)
{
    float* p = which ? g_proj1 : g_proj0;
    long long row = blockIdx.x;
    float* r = p + row*(long long)CH;
    __shared__ float red[256];
    int t = threadIdx.x;
    float a = r[t], b = r[t+256];
    red[t] = fmaxf(a,b); __syncthreads();
    for(int o=128;o>0;o>>=1){ if(t<o) red[t]=fmaxf(red[t],red[t+o]); __syncthreads(); }
    float mx = red[0]; __syncthreads();
    red[t] = expf(a-mx)+expf(b-mx); __syncthreads();
    for(int o=128;o>0;o>>=1){ if(t<o) red[t]+=red[t+o]; __syncthreads(); }
    float lse = logf(red[0]) + mx;
    r[t] = a - lse; r[t+256] = b - lse;
}

__global__ void k_zero_kl(){ g_kl[0]=0.0; g_kl[1]=0.0; }

__global__ void k_kl()
{
    long long tot = (long long)CBN*CH;
    double t1=0,t2=0;
    for (long long i = (long long)blockIdx.x*blockDim.x+threadIdx.x; i<tot;
         i += (long long)gridDim.x*blockDim.x){
        float lf=g_proj0[i], ls=g_proj1[i];
        t1 += (double)(expf(ls)*(ls-lf));
        t2 += (double)(expf(lf)*(lf-ls));
    }
    __shared__ double r1[256], r2[256];
    int t=threadIdx.x; r1[t]=t1; r2[t]=t2; __syncthreads();
    for(int o=128;o>0;o>>=1){ if(t<o){r1[t]+=r1[t+o];r2[t]+=r2[t+o];} __syncthreads(); }
    if(t==0){ atomicAdd(&g_kl[0], r1[0]); atomicAdd(&g_kl[1], r2[0]); }
}

__global__ void k_loss(float* __restrict__ out)
{
    out[0] = (float)(0.5*(g_kl[0]+g_kl[1])/(double)CBN);
}

// ---------------- host orchestration ----------------
// CRITICAL: __device__ symbols passed as kernel ARGUMENTS must be resolved via
// cudaGetSymbolAddress. Naming them directly in host code yields the HOST shadow
// address, which GB300's ATS happily dereferences (host memory!) — silently
// reading zeros and writing results to host RAM instead of the device arrays.
static float* sym_addr(const void* symbol)
{
    void* p = nullptr;
    cudaGetSymbolAddress(&p, symbol);
    return (float*)p;
}

extern "C" void kernel_launch(void* const* d_in, const int* in_sizes, int n_in,
                              void* d_out, int out_size)
{
    const float* x[2]    = {(const float*)d_in[0], (const float*)d_in[1]};
    const float* pri[2]  = {(const float*)d_in[2], (const float*)d_in[3]};
    const float* conn[2] = {(const float*)d_in[4], (const float*)d_in[5]};
    const float* dw      = (const float*)d_in[6];
    const float* wqkv[2] = {(const float*)d_in[7], (const float*)d_in[8]};
    const float* ln_g    = (const float*)d_in[9];
    const float* ln_b    = (const float*)d_in[10];
    const float* ffn_w1  = (const float*)d_in[11];
    const float* ffn_b1  = (const float*)d_in[12];
    const float* ffn_w2  = (const float*)d_in[13];
    const float* ffn_b2  = (const float*)d_in[14];
    const float* pw      = (const float*)d_in[15];
    const float* pb      = (const float*)d_in[16];
    const float* f1w     = (const float*)d_in[17];
    const float* f1b     = (const float*)d_in[18];
    const float* f2w     = (const float*)d_in[19];
    const float* f2b     = (const float*)d_in[20];
    const float* ipw     = (const float*)d_in[21];
    const float* ipb     = (const float*)d_in[22];
    const float* alpha   = (const float*)d_in[23];
    float* out = (float*)d_out;

    // real DEVICE addresses for every symbol passed as a kernel argument
    float* p_z       = sym_addr(g_z);
    float* p_qkv     = sym_addr(g_qkv);
    float* p_pe      = sym_addr(g_pe);
    float* p_h       = sym_addr(g_h);
    float* p_zc      = sym_addr(g_zc);
    float* p_scores  = sym_addr(g_scores);
    float* p_attnout = sym_addr(g_attnout);
    float* p_ffnh    = sym_addr(g_ffnh);
    float* p_ffnout  = sym_addr(g_ffnout);
    float* p_gbar    = sym_addr(g_gbar);
    float* p_tokens  = sym_addr(g_tokens);
    float* p_qkvwg   = sym_addr(g_qkvwg);
    float* p_invmass = sym_addr(g_invmass);

    const int MY_BN  = (CBN + 63) / 64;    // 190
    const int MY_BPN = (CBPN + 63) / 64;   // 569

    k_zero_kl<<<1,1>>>();

    for (int s = 0; s < 2; s++) {
        // 1. pre-attention LN
        k_layernorm<<<CBN,256>>>(x[s], ln_g + s*CH, ln_b + s*CH, p_z);
        // 2. QKV = z @ wqkv
        gemm3<<<24*MY_BN,256>>>(p_z, wqkv[s], nullptr, p_qkv,
            CBN, CH, 3*CH, 24, nullptr, 1, nullptr, 0, 0);
        // 3. prior similarity + mass
        k_prior_reduce<<<CB*CP,256>>>(pri[s], conn[s]);
        k_conn_sumsq<<<CB,256>>>(conn[s]);
        k_sw<<<CB,32>>>();
        // 4. pe = (pri/mass) @ pw + pb
        gemm3<<<8*MY_BPN,256>>>(pri[s], pw, pb, p_pe,
            CBPN, CN, CH, 8, p_invmass, CN, nullptr, 0, 0);
        // 5. fused_nh
        k_fused_nh<<<(X_SZ+255)/256,256>>>();
        // 6. zc = z @ f1w[512:] + f1b
        gemm3<<<8*MY_BN,256>>>(p_z, f1w + CH*CH, f1b, p_zc,
            CBN, CH, CH, 8, nullptr, 1, nullptr, 0, 0);
        // 7. g = gelu(pe @ f1w[:512] + zc)
        gemm3<<<8*MY_BPN,256>>>(p_pe, f1w, nullptr, p_h,
            CBPN, CH, CH, 8, nullptr, 1, p_zc, 2, 1);
        // 8. gbar ; tokens ; qkv_wg
        k_gbar<<<CB*CP,256>>>();
        gemm3<<<8*2,256>>>(p_gbar, f2w, f2b, p_tokens,
            CB*CP, CH, CH, 8, nullptr, 1, nullptr, 0, 0);
        gemm3<<<24*2,256>>>(p_tokens, ipw, ipb, p_qkvwg,
            CB*CP, CH, 3*CH, 24, nullptr, 1, nullptr, 0, 0);
        // 9. tiny MHA -> aw_, msum ; mask
        k_wg_attn<<<CB,64>>>(out + (s ? AWSC_OFF : AWFC_OFF));
        k_mask<<<(CB*CNN+255)/256,256>>>(conn[s], alpha);
        // 10. attention
        k_scores<<<CB*CNH*144,256>>>();
        k_softmax_rows<<<CB*CNH*CN,128>>>(p_scores, CN);
        k_ctx<<<CB*CNH*12,256>>>();
        k_add3<<<(X_SZ+255)/256,256>>>(x[s]);
        // 11. FFN
        k_layernorm<<<CBN,256>>>(p_attnout, ln_g + (2+s)*CH, ln_b + (2+s)*CH, p_z);
        gemm3<<<32*MY_BN,256>>>(p_z, ffn_w1 + (long long)s*CH*4*CH,
            ffn_b1 + s*4*CH, p_ffnh, CBN, CH, 4*CH, 32, nullptr, 1, nullptr, 0, 1);
        gemm3<<<8*MY_BN,256>>>(p_ffnh, ffn_w2 + (long long)s*4*CH*CH,
            ffn_b2 + s*CH, p_ffnout, CBN, 4*CH, CH, 8, nullptr, 1, nullptr, 0, 0);
        // 12. residual + projection for distill
        k_final<<<(X_SZ+255)/256,256>>>(out + (long long)s*X_SZ, dw, s);
    }

    // distillation loss
    k_logsoftmax<<<CBN,256>>>(0);
    k_logsoftmax<<<CBN,256>>>(1);
    k_kl<<<1024,256>>>();
    k_loss<<<1,1>>>(out + LOSS_OFF);
}

// round 6
// speedup vs baseline: 1.1952x; 1.1952x over previous
#include <cuda_runtime.h>
#include <math.h>

// ---------------- problem constants ----------------
#define CB   32
#define CN   379
#define CH   512
#define CNH  8
#define CP   3
#define CWGH 4
#define CHD  64          // CH/CNH
#define CBN  (CB*CN)     // 12128
#define CBPN (CB*CP*CN)  // 36384
#define CNN  (CN*CN)     // 143641

#define X_SZ   (CBN*CH)          // 6209536
#define LOSS_OFF (2*X_SZ)
#define AWFC_OFF (LOSS_OFF+1)
#define AWSC_OFF (AWFC_OFF + CB*CP)

// ---------------- static scratch (zero-init by default) ----------------
static __device__ float g_z[CBN*CH];
static __device__ float g_qkv[CBN*3*CH];
static __device__ float g_pe[(long long)CBPN*CH];
static __device__ float g_h[(long long)CBPN*CH];
static __device__ float g_zc[CBN*CH];
static __device__ float g_fn[CBN*CH];
static __device__ float g_mask[(long long)CB*CNN];
static __device__ float g_scores[(long long)CB*CNH*CNN];
static __device__ float g_ctx[CBN*CH];
static __device__ float g_attnout[CBN*CH];
static __device__ float g_ffnh[(long long)CBN*4*CH];
static __device__ float g_ffnout[CBN*CH];
static __device__ float g_proj0[CBN*CH];
static __device__ float g_proj1[CBN*CH];
static __device__ float g_gbar[CB*CP*CH];
static __device__ float g_gpart[CB*CP*8*CH];
static __device__ float g_tokens[CB*CP*CH];
static __device__ float g_qkvwg[CB*CP*3*CH];
static __device__ float g_dot[CB*CP], g_psq[CB*CP], g_pabs[CB*CP], g_csq[CB];
static __device__ float g_sw[CB*CP], g_invmass[CB*CP], g_msum[CB];
static __device__ double g_kl[2];

// ---------------- tf32 tensor-core GEMM, 1-D grid ----------------
// C = act(A@W + bias + res). A:(M,K) row-major fp32, W:(K,Nc) row-major fp32.
// Block tile 128x64, 256 threads (8 warps as 4m x 2n), warp tile 32x32,
// mma.sync m16n8k8 tf32, k-chunk 32. Nc must be a multiple of 64.
// resMode: 0 none, 1 res[gm*Nc+gn], 2 res[(b*CN+n)*Nc+gn] with gm=(b*CP+p)*CN+n.
__global__ void gemm_tc(const float* __restrict__ A, const float* __restrict__ W,
                        const float* __restrict__ bias, float* __restrict__ C,
                        int M, int K, int Nc, int gridNx,
                        const float* __restrict__ rowScale, int rowScaleDiv,
                        const float* __restrict__ res, int resMode, int act)
{
    __shared__ unsigned As[128][36];   // tf32 bits, stride 36 -> conflict-free frag loads
    __shared__ unsigned Ws[32][72];    // tf32 bits, stride 72 -> conflict-free frag loads
    const int t    = threadIdx.x;
    const int bx   = blockIdx.x % gridNx;
    const int by   = blockIdx.x / gridNx;
    const int m0   = by * 128;
    const int n0   = bx * 64;
    const int lane = t & 31, warp = t >> 5;
    const int wm   = warp >> 1;        // 0..3
    const int wn   = warp & 1;         // 0..1
    const int gid  = lane >> 2;        // 0..7
    const int tid4 = lane & 3;         // 0..3

    // loaders
    const int ar = t >> 1;             // 0..127
    const int ac = (t & 1) * 16;       // 0 or 16
    const int wr = t >> 3;             // 0..31
    const int wc = (t & 7) * 8;        // 0..56

    const int gmA = m0 + ar;
    float sc = 1.f;
    if (rowScale && gmA < M) sc = rowScale[gmA / rowScaleDiv];
    const float* arow = A + (long long)gmA * K;

    float c[2][4][4];
    #pragma unroll
    for (int i=0;i<2;i++)
        #pragma unroll
        for (int j=0;j<4;j++)
            #pragma unroll
            for (int k=0;k<4;k++) c[i][j][k]=0.f;

    for (int kk = 0; kk < K; kk += 32) {
        // stage A tile 128x32
        #pragma unroll
        for (int u = 0; u < 16; u++) {
            int gk = kk + ac + u;
            float v = (gmA < M && gk < K) ? arow[gk] * sc : 0.f;
            unsigned tv; asm("cvt.rna.tf32.f32 %0, %1;" : "=r"(tv) : "f"(v));
            As[ar][ac + u] = tv;
        }
        // stage W tile 32x64
        {
            int gk = kk + wr;
            #pragma unroll
            for (int u = 0; u < 8; u++) {
                int gn = n0 + wc + u;
                float v = (gk < K && gn < Nc) ? W[(long long)gk * Nc + gn] : 0.f;
                unsigned tv; asm("cvt.rna.tf32.f32 %0, %1;" : "=r"(tv) : "f"(v));
                Ws[wr][wc + u] = tv;
            }
        }
        __syncthreads();
        #pragma unroll
        for (int k8 = 0; k8 < 32; k8 += 8) {
            unsigned a[2][4], b[4][2];
            #pragma unroll
            for (int ma = 0; ma < 2; ma++) {
                int rb = wm*32 + ma*16;
                a[ma][0] = As[rb + gid    ][k8 + tid4    ];
                a[ma][1] = As[rb + gid + 8][k8 + tid4    ];
                a[ma][2] = As[rb + gid    ][k8 + tid4 + 4];
                a[ma][3] = As[rb + gid + 8][k8 + tid4 + 4];
            }
            #pragma unroll
            for (int nb = 0; nb < 4; nb++) {
                int cn = wn*32 + nb*8 + gid;
                b[nb][0] = Ws[k8 + tid4    ][cn];
                b[nb][1] = Ws[k8 + tid4 + 4][cn];
            }
            #pragma unroll
            for (int ma = 0; ma < 2; ma++)
                #pragma unroll
                for (int nb = 0; nb < 4; nb++)
                    asm volatile(
                        "mma.sync.aligned.m16n8k8.row.col.f32.tf32.tf32.f32 "
                        "{%0,%1,%2,%3}, {%4,%5,%6,%7}, {%8,%9}, {%0,%1,%2,%3};"
                        : "+f"(c[ma][nb][0]), "+f"(c[ma][nb][1]),
                          "+f"(c[ma][nb][2]), "+f"(c[ma][nb][3])
                        : "r"(a[ma][0]), "r"(a[ma][1]), "r"(a[ma][2]), "r"(a[ma][3]),
                          "r"(b[nb][0]), "r"(b[nb][1]));
        }
        __syncthreads();
    }

    // epilogue
    #pragma unroll
    for (int ma = 0; ma < 2; ma++) {
        #pragma unroll
        for (int rr = 0; rr < 2; rr++) {
            int gm = m0 + wm*32 + ma*16 + gid + rr*8;
            if (gm >= M) continue;
            long long resBase = 0;
            if (resMode == 1) resBase = (long long)gm * Nc;
            else if (resMode == 2) {
                int bb = gm / (CP * CN);
                int nn = gm % CN;
                resBase = ((long long)bb * CN + nn) * (long long)Nc;
            }
            #pragma unroll
            for (int nb = 0; nb < 4; nb++) {
                #pragma unroll
                for (int cc = 0; cc < 2; cc++) {
                    int gn = n0 + wn*32 + nb*8 + 2*tid4 + cc;
                    float v = c[ma][nb][rr*2 + cc];
                    if (bias) v += bias[gn];
                    if (resMode) v += res[resBase + gn];
                    if (act) v = 0.5f * v * (1.f + erff(v * 0.70710678118654752f));
                    C[(long long)gm * Nc + gn] = v;
                }
            }
        }
    }
}

// ---------------- layernorm: one block per row, CH=512, 256 threads ----------------
__global__ void k_layernorm(const float* __restrict__ x, const float* __restrict__ g,
                            const float* __restrict__ b, float* __restrict__ z)
{
    int row = blockIdx.x;
    const float* xr = x + (long long)row*CH;
    float* zr = z + (long long)row*CH;
    __shared__ float red[256];
    int t = threadIdx.x;
    float v0 = xr[t], v1 = xr[t+256];
    red[t] = v0+v1; __syncthreads();
    for (int o=128;o>0;o>>=1){ if(t<o) red[t]+=red[t+o]; __syncthreads(); }
    float mean = red[0]*(1.f/CH); __syncthreads();
    float d0=v0-mean, d1=v1-mean;
    red[t]=d0*d0+d1*d1; __syncthreads();
    for (int o=128;o>0;o>>=1){ if(t<o) red[t]+=red[t+o]; __syncthreads(); }
    float rstd = rsqrtf(red[0]*(1.f/CH) + 1e-5f);
    zr[t]     = d0*rstd*g[t]     + b[t];
    zr[t+256] = d1*rstd*g[t+256] + b[t+256];
}

// ---------------- prior reductions ----------------
__global__ void k_prior_reduce(const float* __restrict__ pri, const float* __restrict__ conn)
{
    int bp = blockIdx.x; int b = bp / CP;
    const float* p = pri + (long long)bp*CNN;
    const float* c = conn + (long long)b*CNN;
    float dot=0, sq=0, ab=0;
    for (int i = threadIdx.x; i < CNN; i += blockDim.x) {
        float pv = p[i];
        dot += pv*c[i]; sq += pv*pv; ab += fabsf(pv);
    }
    __shared__ float r1[256], r2[256], r3[256];
    int t=threadIdx.x; r1[t]=dot;r2[t]=sq;r3[t]=ab; __syncthreads();
    for(int o=128;o>0;o>>=1){ if(t<o){r1[t]+=r1[t+o];r2[t]+=r2[t+o];r3[t]+=r3[t+o];} __syncthreads(); }
    if(t==0){ g_dot[bp]=r1[0]; g_psq[bp]=r2[0]; g_pabs[bp]=r3[0]; }
}

__global__ void k_conn_sumsq(const float* __restrict__ conn)
{
    int b = blockIdx.x;
    const float* c = conn + (long long)b*CNN;
    float sq=0;
    for (int i = threadIdx.x; i < CNN; i += blockDim.x) { float v=c[i]; sq += v*v; }
    __shared__ float r[256];
    int t=threadIdx.x; r[t]=sq; __syncthreads();
    for(int o=128;o>0;o>>=1){ if(t<o) r[t]+=r[t+o]; __syncthreads(); }
    if(t==0) g_csq[b]=r[0];
}

__global__ void k_sw()
{
    if (threadIdx.x) return;
    int b = blockIdx.x;
    float cn = fmaxf(sqrtf(g_csq[b]), 1e-12f);
    float s[CP], mx=-1e30f;
    for (int p=0;p<CP;p++){
        float pn = fmaxf(sqrtf(g_psq[b*CP+p]), 1e-12f);
        s[p] = g_dot[b*CP+p]/(cn*pn);
        mx = fmaxf(mx, s[p]);
    }
    float sum=0;
    for (int p=0;p<CP;p++){ s[p]=expf(s[p]-mx); sum+=s[p]; }
    for (int p=0;p<CP;p++){
        g_sw[b*CP+p]=s[p]/sum;
        g_invmass[b*CP+p] = 1.f/g_pabs[b*CP+p];
    }
}

// ---------------- fused_nh[b,n,c] = sum_p sw[b,p]*pe[b,p,n,c] ----------------
__global__ void k_fused_nh()
{
    long long idx = (long long)blockIdx.x*blockDim.x + threadIdx.x;
    if (idx >= (long long)CBN*CH) return;
    int c = (int)(idx % CH);
    long long bn = idx / CH;
    int b = (int)(bn / CN), n = (int)(bn % CN);
    float acc=0;
    #pragma unroll
    for (int p=0;p<CP;p++)
        acc += g_sw[b*CP+p]*g_pe[((long long)(b*CP+p)*CN + n)*CH + c];
    g_fn[idx]=acc;
}

// ---------------- gbar two-stage: partials over 48-row chunks, then reduce ----------------
__global__ void k_gbar_part()
{
    int blk = blockIdx.x;           // CB*CP*8
    int bp = blk >> 3, ch = blk & 7;
    int c = threadIdx.x;
    int nlo = ch*48, nhi = nlo+48; if (nhi > CN) nhi = CN;
    float a0=0, a1=0;
    for (int n=nlo; n<nhi; n++){
        const float* r = g_h + ((long long)bp*CN+n)*CH;
        a0 += r[c]; a1 += r[c+256];
    }
    g_gpart[(long long)blk*CH + c]       = a0;
    g_gpart[(long long)blk*CH + c + 256] = a1;
}

__global__ void k_gbar_fin()
{
    int bp = blockIdx.x; int c = threadIdx.x;
    float a0=0, a1=0;
    #pragma unroll
    for (int ch=0; ch<8; ch++){
        const float* r = g_gpart + (long long)(bp*8+ch)*CH;
        a0 += r[c]; a1 += r[c+256];
    }
    g_gbar[bp*CH+c]     = a0*(1.f/CN);
    g_gbar[bp*CH+c+256] = a1*(1.f/CN);
}

// ---------------- tiny weight-gen MHA -> aw_, msum ----------------
__global__ void k_wg_attn(float* __restrict__ aw_out)
{
    int b = blockIdx.x;
    __shared__ float logit[CWGH*CP*CP];   // 36 floats
    int t = threadIdx.x;                  // 64 threads
    if (t < CWGH*CP*CP) {
        int h = t/(CP*CP); int i = (t/CP)%CP; int j = t%CP;
        const float* q = g_qkvwg + (long long)(b*CP+i)*3*CH + h*128;
        const float* k = g_qkvwg + (long long)(b*CP+j)*3*CH + CH + h*128;
        float d=0;
        for (int x=0;x<128;x++) d += q[x]*k[x];
        logit[t] = d*0.08838834764831845f;   // 1/sqrt(128)
    }
    __syncthreads();
    if (t==0) {
        float aw[CP]={0,0,0};
        for (int h=0;h<CWGH;h++) for (int i=0;i<CP;i++) {
            float mx=-1e30f;
            for (int j=0;j<CP;j++) mx=fmaxf(mx, logit[(h*CP+i)*CP+j]);
            float e[CP], s=0;
            for (int j=0;j<CP;j++){ e[j]=expf(logit[(h*CP+i)*CP+j]-mx); s+=e[j]; }
            for (int j=0;j<CP;j++) aw[j]+= e[j]/s;
        }
        for (int j=0;j<CP;j++) aw[j] *= (1.f/(CWGH*CP));
        float mx=-1e30f;
        for (int j=0;j<CP;j++) mx=fmaxf(mx, aw[j]);
        float s=0, e[CP];
        for (int j=0;j<CP;j++){ e[j]=expf((aw[j]-mx)*100.f); s+=e[j]; }  // temp 0.01
        float msum=0;
        for (int j=0;j<CP;j++){ float a=e[j]/s; aw_out[b*CP+j]=a; msum+=a; }
        g_msum[b]=msum;
    }
}

// ---------------- mask = tanh(a/2*msum + (1-a/2)*conn) ----------------
__global__ void k_mask(const float* __restrict__ conn, const float* __restrict__ alpha)
{
    long long idx = (long long)blockIdx.x*blockDim.x + threadIdx.x;
    if (idx >= (long long)CB*CNN) return;
    int b = (int)(idx / CNN);
    float a2 = alpha[0]*0.5f;
    g_mask[idx] = tanhf(a2*g_msum[b] + (1.f-a2)*conn[idx]);
}

// ---------------- scores: 1-D grid, 256 thr, 32x32 tile, k-chunk 16 ----------------
__global__ void k_scores()
{
    int blk = blockIdx.x;            // 256*144 blocks
    int bh = blk / 144;
    int r  = blk % 144;
    int b = bh >> 3, h = bh & 7;
    int i0 = (r / 12) * 32, j0 = (r % 12) * 32;
    __shared__ float Qs[32][17], Ks[32][17];
    int t = threadIdx.x;
    int lr = t >> 3;                 // 0..31
    int lc = (t & 7) * 2;            // 0..14
    int ti = t >> 4, tj = t & 15;
    float a00=0,a01=0,a10=0,a11=0;
    int gi_l = i0 + lr, gj_l = j0 + lr;
    for (int k0 = 0; k0 < CHD; k0 += 16) {
        #pragma unroll
        for (int u=0;u<2;u++){
            Qs[lr][lc+u] = (gi_l<CN)? g_qkv[(long long)(b*CN+gi_l)*3*CH + h*CHD + k0+lc+u] : 0.f;
            Ks[lr][lc+u] = (gj_l<CN)? g_qkv[(long long)(b*CN+gj_l)*3*CH + CH + h*CHD + k0+lc+u] : 0.f;
        }
        __syncthreads();
        #pragma unroll
        for (int x=0;x<16;x++){
            float q0=Qs[ti][x], q1=Qs[ti+16][x];
            float kv0=Ks[tj][x], kv1=Ks[tj+16][x];
            a00+=q0*kv0; a01+=q0*kv1; a10+=q1*kv0; a11+=q1*kv1;
        }
        __syncthreads();
    }
    float* srow = g_scores + (long long)bh*CNN;
    const float* mrow = g_mask + (long long)b*CNN;
    int i_[2] = {i0+ti, i0+ti+16};
    int j_[2] = {j0+tj, j0+tj+16};
    float av[2][2] = {{a00,a01},{a10,a11}};
    #pragma unroll
    for (int ii=0;ii<2;ii++){
        if (i_[ii] >= CN) continue;
        #pragma unroll
        for (int jj=0;jj<2;jj++){
            if (j_[jj] >= CN) continue;
            long long o = (long long)i_[ii]*CN + j_[jj];
            srow[o] = 0.125f*av[ii][jj]*(1.f + mrow[o]);
        }
    }
}

__global__ void k_softmax_rows(float* __restrict__ s, int cols)
{
    long long row = blockIdx.x;
    float* r = s + row*(long long)cols;
    __shared__ float red[128];
    int t = threadIdx.x;
    float mx = -1e30f;
    for (int c=t;c<cols;c+=128) mx = fmaxf(mx, r[c]);
    red[t]=mx; __syncthreads();
    for(int o=64;o>0;o>>=1){ if(t<o) red[t]=fmaxf(red[t],red[t+o]); __syncthreads(); }
    mx = red[0]; __syncthreads();
    float sum=0;
    for (int c=t;c<cols;c+=128){ float e=expf(r[c]-mx); r[c]=e; sum+=e; }
    red[t]=sum; __syncthreads();
    for(int o=64;o>0;o>>=1){ if(t<o) red[t]+=red[t+o]; __syncthreads(); }
    float inv = 1.f/red[0];
    for (int c=t;c<cols;c+=128) r[c]*=inv;
}

// ---------------- ctx = P @ V, 1-D grid, 256 thr, j-chunk 16 ----------------
__global__ void k_ctx()
{
    int blk = blockIdx.x;            // 32*8*12 = 3072 blocks
    int b = blk / 96;
    int rem = blk % 96;
    int h = rem / 12;
    int i0 = (rem % 12) * 32;
    int t = threadIdx.x;
    int tx = t & 63;                 // d
    int ty = t >> 6;                 // 0..3
    __shared__ float Ps[32][17], Vs[16][65];
    float acc[8]={};
    const float* srow = g_scores + (long long)(b*CNH+h)*CNN;
    int pr = t >> 3, pc = (t & 7) * 2;   // Ps loader
    int vr = t >> 4, vc = (t & 15) * 4;  // Vs loader
    for (int j0=0;j0<CN;j0+=16) {
        int gi = i0 + pr;
        #pragma unroll
        for (int u=0;u<2;u++){
            int gj = j0 + pc + u;
            Ps[pr][pc+u] = (gi<CN && gj<CN) ? srow[(long long)gi*CN+gj] : 0.f;
        }
        int gj = j0 + vr;
        #pragma unroll
        for (int u=0;u<4;u++)
            Vs[vr][vc+u] = (gj<CN) ? g_qkv[(long long)(b*CN+gj)*3*CH + 2*CH + h*CHD + vc+u] : 0.f;
        __syncthreads();
        #pragma unroll
        for (int jj=0;jj<16;jj++){
            float vv = Vs[jj][tx];
            #pragma unroll
            for (int ii=0;ii<8;ii++)
                acc[ii] += Ps[ty+4*ii][jj]*vv;
        }
        __syncthreads();
    }
    #pragma unroll
    for (int ii=0;ii<8;ii++){
        int gi = i0+ty+4*ii;
        if (gi<CN) g_ctx[(long long)(b*CN+gi)*CH + h*CHD + tx] = acc[ii];
    }
}

// ---------------- elementwise combines ----------------
__global__ void k_add3(const float* __restrict__ x)
{
    long long idx = (long long)blockIdx.x*blockDim.x + threadIdx.x;
    if (idx >= (long long)CBN*CH) return;
    g_attnout[idx] = x[idx] + g_ctx[idx] + g_fn[idx];
}

__global__ void k_final(float* __restrict__ outx, const float* __restrict__ dwp, int sidx)
{
    long long idx = (long long)blockIdx.x*blockDim.x + threadIdx.x;
    if (idx >= (long long)CBN*CH) return;
    float w = dwp[sidx];
    float f = g_ffnout[idx];
    float xn = g_attnout[idx] + f;
    outx[idx] = xn;
    float pv = w*f + (1.f-w)*xn;
    if (sidx == 0) g_proj0[idx] = pv; else g_proj1[idx] = pv;
}

__global__ void k_logsoftmax(int which)
{
    float* p = which ? g_proj1 : g_proj0;
    long long row = blockIdx.x;
    float* r = p + row*(long long)CH;
    __shared__ float red[256];
    int t = threadIdx.x;
    float a = r[t], b = r[t+256];
    red[t] = fmaxf(a,b); __syncthreads();
    for(int o=128;o>0;o>>=1){ if(t<o) red[t]=fmaxf(red[t],red[t+o]); __syncthreads(); }
    float mx = red[0]; __syncthreads();
    red[t] = expf(a-mx)+expf(b-mx); __syncthreads();
    for(int o=128;o>0;o>>=1){ if(t<o) red[t]+=red[t+o]; __syncthreads(); }
    float lse = logf(red[0]) + mx;
    r[t] = a - lse; r[t+256] = b - lse;
}

__global__ void k_zero_kl(){ g_kl[0]=0.0; g_kl[1]=0.0; }

__global__ void k_kl()
{
    long long tot = (long long)CBN*CH;
    double t1=0,t2=0;
    for (long long i = (long long)blockIdx.x*blockDim.x+threadIdx.x; i<tot;
         i += (long long)gridDim.x*blockDim.x){
        float lf=g_proj0[i], ls=g_proj1[i];
        t1 += (double)(expf(ls)*(ls-lf));
        t2 += (double)(expf(lf)*(lf-ls));
    }
    __shared__ double r1[256], r2[256];
    int t=threadIdx.x; r1[t]=t1; r2[t]=t2; __syncthreads();
    for(int o=128;o>0;o>>=1){ if(t<o){r1[t]+=r1[t+o];r2[t]+=r2[t+o];} __syncthreads(); }
    if(t==0){ atomicAdd(&g_kl[0], r1[0]); atomicAdd(&g_kl[1], r2[0]); }
}

__global__ void k_loss(float* __restrict__ out)
{
    out[0] = (float)(0.5*(g_kl[0]+g_kl[1])/(double)CBN);
}

// ---------------- host orchestration ----------------
// CRITICAL: __device__ symbols passed as kernel ARGUMENTS must be resolved via
// cudaGetSymbolAddress (host shadow address + GB300 ATS silently reads host RAM).
static float* sym_addr(const void* symbol)
{
    void* p = nullptr;
    cudaGetSymbolAddress(&p, symbol);
    return (float*)p;
}

extern "C" void kernel_launch(void* const* d_in, const int* in_sizes, int n_in,
                              void* d_out, int out_size)
{
    const float* x[2]    = {(const float*)d_in[0], (const float*)d_in[1]};
    const float* pri[2]  = {(const float*)d_in[2], (const float*)d_in[3]};
    const float* conn[2] = {(const float*)d_in[4], (const float*)d_in[5]};
    const float* dw      = (const float*)d_in[6];
    const float* wqkv[2] = {(const float*)d_in[7], (const float*)d_in[8]};
    const float* ln_g    = (const float*)d_in[9];
    const float* ln_b    = (const float*)d_in[10];
    const float* ffn_w1  = (const float*)d_in[11];
    const float* ffn_b1  = (const float*)d_in[12];
    const float* ffn_w2  = (const float*)d_in[13];
    const float* ffn_b2  = (const float*)d_in[14];
    const float* pw      = (const float*)d_in[15];
    const float* pb      = (const float*)d_in[16];
    const float* f1w     = (const float*)d_in[17];
    const float* f1b     = (const float*)d_in[18];
    const float* f2w     = (const float*)d_in[19];
    const float* f2b     = (const float*)d_in[20];
    const float* ipw     = (const float*)d_in[21];
    const float* ipb     = (const float*)d_in[22];
    const float* alpha   = (const float*)d_in[23];
    float* out = (float*)d_out;

    float* p_z       = sym_addr(g_z);
    float* p_qkv     = sym_addr(g_qkv);
    float* p_pe      = sym_addr(g_pe);
    float* p_h       = sym_addr(g_h);
    float* p_zc      = sym_addr(g_zc);
    float* p_scores  = sym_addr(g_scores);
    float* p_attnout = sym_addr(g_attnout);
    float* p_ffnh    = sym_addr(g_ffnh);
    float* p_ffnout  = sym_addr(g_ffnout);
    float* p_gbar    = sym_addr(g_gbar);
    float* p_tokens  = sym_addr(g_tokens);
    float* p_qkvwg   = sym_addr(g_qkvwg);
    float* p_invmass = sym_addr(g_invmass);

    const int MB_BN  = (CBN  + 127) / 128;   // 95
    const int MB_BPN = (CBPN + 127) / 128;   // 285

    k_zero_kl<<<1,1>>>();

    for (int s = 0; s < 2; s++) {
        // 1. pre-attention LN
        k_layernorm<<<CBN,256>>>(x[s], ln_g + s*CH, ln_b + s*CH, p_z);
        // 2. QKV = z @ wqkv  (Nc=1536 -> 24 n-blocks)
        gemm_tc<<<24*MB_BN,256>>>(p_z, wqkv[s], nullptr, p_qkv,
            CBN, CH, 3*CH, 24, nullptr, 1, nullptr, 0, 0);
        // 3. prior similarity + mass
        k_prior_reduce<<<CB*CP,256>>>(pri[s], conn[s]);
        k_conn_sumsq<<<CB,256>>>(conn[s]);
        k_sw<<<CB,32>>>();
        // 4. pe = (pri/mass) @ pw + pb
        gemm_tc<<<8*MB_BPN,256>>>(pri[s], pw, pb, p_pe,
            CBPN, CN, CH, 8, p_invmass, CN, nullptr, 0, 0);
        // 5. fused_nh
        k_fused_nh<<<(X_SZ+255)/256,256>>>();
        // 6. zc = z @ f1w[512:] + f1b
        gemm_tc<<<8*MB_BN,256>>>(p_z, f1w + CH*CH, f1b, p_zc,
            CBN, CH, CH, 8, nullptr, 1, nullptr, 0, 0);
        // 7. g = gelu(pe @ f1w[:512] + zc)
        gemm_tc<<<8*MB_BPN,256>>>(p_pe, f1w, nullptr, p_h,
            CBPN, CH, CH, 8, nullptr, 1, p_zc, 2, 1);
        // 8. gbar (two-stage) ; tokens ; qkv_wg
        k_gbar_part<<<CB*CP*8,256>>>();
        k_gbar_fin<<<CB*CP,256>>>();
        gemm_tc<<<8*1,256>>>(p_gbar, f2w, f2b, p_tokens,
            CB*CP, CH, CH, 8, nullptr, 1, nullptr, 0, 0);
        gemm_tc<<<24*1,256>>>(p_tokens, ipw, ipb, p_qkvwg,
            CB*CP, CH, 3*CH, 24, nullptr, 1, nullptr, 0, 0);
        // 9. tiny MHA -> aw_, msum ; mask
        k_wg_attn<<<CB,64>>>(out + (s ? AWSC_OFF : AWFC_OFF));
        k_mask<<<(CB*CNN+255)/256,256>>>(conn[s], alpha);
        // 10. attention
        k_scores<<<CB*CNH*144,256>>>();
        k_softmax_rows<<<CB*CNH*CN,128>>>(p_scores, CN);
        k_ctx<<<CB*CNH*12,256>>>();
        k_add3<<<(X_SZ+255)/256,256>>>(x[s]);
        // 11. FFN
        k_layernorm<<<CBN,256>>>(p_attnout, ln_g + (2+s)*CH, ln_b + (2+s)*CH, p_z);
        gemm_tc<<<32*MB_BN,256>>>(p_z, ffn_w1 + (long long)s*CH*4*CH,
            ffn_b1 + s*4*CH, p_ffnh, CBN, CH, 4*CH, 32, nullptr, 1, nullptr, 0, 1);
        gemm_tc<<<8*MB_BN,256>>>(p_ffnh, ffn_w2 + (long long)s*4*CH*CH,
            ffn_b2 + s*CH, p_ffnout, CBN, 4*CH, CH, 8, nullptr, 1, nullptr, 0, 0);
        // 12. residual + projection for distill
        k_final<<<(X_SZ+255)/256,256>>>(out + (long long)s*X_SZ, dw, s);
    }

    // distillation loss
    k_logsoftmax<<<CBN,256>>>(0);
    k_logsoftmax<<<CBN,256>>>(1);
    k_kl<<<1024,256>>>();
    k_loss<<<1,1>>>(out + LOSS_OFF);
}

// round 7
// speedup vs baseline: 2.1541x; 1.8023x over previous
#include <cuda_runtime.h>
#include <math.h>

// ---------------- problem constants ----------------
#define CB   32
#define CN   379
#define CH   512
#define CNH  8
#define CP   3
#define CWGH 4
#define CHD  64          // CH/CNH
#define CBN  (CB*CN)     // 12128
#define CBPN (CB*CP*CN)  // 36384
#define CNN  (CN*CN)     // 143641

#define X_SZ   (CBN*CH)          // 6209536
#define LOSS_OFF (2*X_SZ)
#define AWFC_OFF (LOSS_OFF+1)
#define AWSC_OFF (AWFC_OFF + CB*CP)

// ---------------- static scratch (zero-init by default) ----------------
static __device__ float g_z[CBN*CH];
static __device__ float g_qkv[CBN*3*CH];
static __device__ float g_pe[(long long)CBPN*CH];
static __device__ float g_h[(long long)CBPN*CH];
static __device__ float g_zc[CBN*CH];
static __device__ float g_fn[CBN*CH];
static __device__ float g_mask[(long long)CB*CNN];
static __device__ float g_scores[(long long)CB*CNH*CNN];
static __device__ float g_ctx[CBN*CH];
static __device__ float g_attnout[CBN*CH];
static __device__ float g_ffnh[(long long)CBN*4*CH];
static __device__ float g_ffnout[CBN*CH];
static __device__ float g_proj0[CBN*CH];
static __device__ float g_proj1[CBN*CH];
static __device__ float g_gbar[CB*CP*CH];
static __device__ float g_gpart[CB*CP*8*CH];
static __device__ float g_tokens[CB*CP*CH];
static __device__ float g_qkvwg[CB*CP*3*CH];
static __device__ float g_dot[CB*CP], g_psq[CB*CP], g_pabs[CB*CP], g_csq[CB];
static __device__ float g_sw[CB*CP], g_invmass[CB*CP], g_msum[CB];
static __device__ double g_kl[2];

__device__ __forceinline__ unsigned to_tf32(float v)
{
    unsigned r; asm("cvt.rna.tf32.f32 %0, %1;" : "=r"(r) : "f"(v)); return r;
}

// ---------------- tf32 tensor-core GEMM, 1-D grid ----------------
// C = act(A@W + bias + res). A:(M,K) row-major fp32, W:(K,Nc) row-major fp32.
// Block tile 128x128, 256 threads = 8 warps (2m x 4n), warp tile 64x32,
// mma.sync m16n8k8 tf32, k-chunk 32. Nc must be a multiple of 128.
// Coalesced float4 staging; scalar fallback when K%4 != 0 (misaligned rows).
// resMode: 0 none, 1 res[gm*Nc+gn], 2 res[(b*CN+n)*Nc+gn] with gm=(b*CP+p)*CN+n.
__global__ void __launch_bounds__(256,2)
gemm_tc(const float* __restrict__ A, const float* __restrict__ W,
        const float* __restrict__ bias, float* __restrict__ C,
        int M, int K, int Nc, int gridNx,
        const float* __restrict__ rowScale, int rowScaleDiv,
        const float* __restrict__ res, int resMode, int act)
{
    __shared__ unsigned As[128][36];    // conflict-free frag reads (36%32=4)
    __shared__ unsigned Ws[32][136];    // conflict-free frag reads (136%32=8)
    const int t    = threadIdx.x;
    const int bx   = blockIdx.x % gridNx;
    const int by   = blockIdx.x / gridNx;
    const int m0   = by * 128;
    const int n0   = bx * 128;
    const int lane = t & 31, warp = t >> 5;
    const int wm   = warp >> 2;          // 0..1
    const int wn   = warp & 3;           // 0..3
    const int gid  = lane >> 2;          // 0..7
    const int tid4 = lane & 3;           // 0..3

    // A loader: warp = 4 rows x 128B contiguous (coalesced)
    const int ac4 = t & 7;               // float4 col 0..7
    const int ar0 = t >> 3;              // row 0..31, +32 per v
    // W loader: warp = 1 row x 512B contiguous (coalesced)
    const int wc4 = t & 31;              // float4 col 0..31
    const int wr0 = t >> 5;              // row 0..7, +8 per v

    const bool k4ok = (K & 3) == 0;

    float c[4][4][4];
    #pragma unroll
    for (int i=0;i<4;i++)
        #pragma unroll
        for (int j=0;j<4;j++)
            #pragma unroll
            for (int k=0;k<4;k++) c[i][j][k]=0.f;

    for (int kk = 0; kk < K; kk += 32) {
        // ---- stage A tile 128x32 ----
        #pragma unroll
        for (int v = 0; v < 4; v++) {
            int row = ar0 + 32*v;
            int gm  = m0 + row;
            int gk  = kk + ac4*4;
            float sc = 1.f;
            if (rowScale && gm < M) sc = rowScale[gm / rowScaleDiv];
            float4 val = make_float4(0.f,0.f,0.f,0.f);
            if (gm < M) {
                const float* ap = A + (long long)gm*K;
                if (k4ok) {
                    if (gk < K) val = *(const float4*)(ap + gk);
                } else {
                    if (gk   < K) val.x = ap[gk];
                    if (gk+1 < K) val.y = ap[gk+1];
                    if (gk+2 < K) val.z = ap[gk+2];
                    if (gk+3 < K) val.w = ap[gk+3];
                }
            }
            unsigned* dst = &As[row][ac4*4];
            dst[0] = to_tf32(val.x*sc);
            dst[1] = to_tf32(val.y*sc);
            dst[2] = to_tf32(val.z*sc);
            dst[3] = to_tf32(val.w*sc);
        }
        // ---- stage W tile 32x128 ----
        #pragma unroll
        for (int v = 0; v < 4; v++) {
            int row = wr0 + 8*v;
            int gk  = kk + row;
            int gn  = n0 + wc4*4;
            float4 val = make_float4(0.f,0.f,0.f,0.f);
            if (gk < K) val = *(const float4*)(W + (long long)gk*Nc + gn);
            unsigned* dst = &Ws[row][wc4*4];
            dst[0] = to_tf32(val.x);
            dst[1] = to_tf32(val.y);
            dst[2] = to_tf32(val.z);
            dst[3] = to_tf32(val.w);
        }
        __syncthreads();
        #pragma unroll
        for (int k8 = 0; k8 < 32; k8 += 8) {
            unsigned a[4][4], b[4][2];
            #pragma unroll
            for (int ma = 0; ma < 4; ma++) {
                int rb = wm*64 + ma*16;
                a[ma][0] = As[rb + gid    ][k8 + tid4    ];
                a[ma][1] = As[rb + gid + 8][k8 + tid4    ];
                a[ma][2] = As[rb + gid    ][k8 + tid4 + 4];
                a[ma][3] = As[rb + gid + 8][k8 + tid4 + 4];
            }
            #pragma unroll
            for (int nb = 0; nb < 4; nb++) {
                int cn = wn*32 + nb*8 + gid;
                b[nb][0] = Ws[k8 + tid4    ][cn];
                b[nb][1] = Ws[k8 + tid4 + 4][cn];
            }
            #pragma unroll
            for (int ma = 0; ma < 4; ma++)
                #pragma unroll
                for (int nb = 0; nb < 4; nb++)
                    asm volatile(
                        "mma.sync.aligned.m16n8k8.row.col.f32.tf32.tf32.f32 "
                        "{%0,%1,%2,%3}, {%4,%5,%6,%7}, {%8,%9}, {%0,%1,%2,%3};"
                        : "+f"(c[ma][nb][0]), "+f"(c[ma][nb][1]),
                          "+f"(c[ma][nb][2]), "+f"(c[ma][nb][3])
                        : "r"(a[ma][0]), "r"(a[ma][1]), "r"(a[ma][2]), "r"(a[ma][3]),
                          "r"(b[nb][0]), "r"(b[nb][1]));
        }
        __syncthreads();
    }

    // ---- epilogue ----
    #pragma unroll
    for (int ma = 0; ma < 4; ma++) {
        #pragma unroll
        for (int rr = 0; rr < 2; rr++) {
            int gm = m0 + wm*64 + ma*16 + gid + rr*8;
            if (gm >= M) continue;
            long long resBase = 0;
            if (resMode == 1) resBase = (long long)gm * Nc;
            else if (resMode == 2) {
                int bb = gm / (CP * CN);
                int nn = gm % CN;
                resBase = ((long long)bb * CN + nn) * (long long)Nc;
            }
            #pragma unroll
            for (int nb = 0; nb < 4; nb++) {
                #pragma unroll
                for (int cc = 0; cc < 2; cc++) {
                    int gn = n0 + wn*32 + nb*8 + 2*tid4 + cc;
                    float v = c[ma][nb][rr*2 + cc];
                    if (bias) v += bias[gn];
                    if (resMode) v += res[resBase + gn];
                    if (act) v = 0.5f * v * (1.f + erff(v * 0.70710678118654752f));
                    C[(long long)gm * Nc + gn] = v;
                }
            }
        }
    }
}

// ---------------- layernorm: one block per row, CH=512, 256 threads ----------------
__global__ void k_layernorm(const float* __restrict__ x, const float* __restrict__ g,
                            const float* __restrict__ b, float* __restrict__ z)
{
    int row = blockIdx.x;
    const float* xr = x + (long long)row*CH;
    float* zr = z + (long long)row*CH;
    __shared__ float red[256];
    int t = threadIdx.x;
    float v0 = xr[t], v1 = xr[t+256];
    red[t] = v0+v1; __syncthreads();
    for (int o=128;o>0;o>>=1){ if(t<o) red[t]+=red[t+o]; __syncthreads(); }
    float mean = red[0]*(1.f/CH); __syncthreads();
    float d0=v0-mean, d1=v1-mean;
    red[t]=d0*d0+d1*d1; __syncthreads();
    for (int o=128;o>0;o>>=1){ if(t<o) red[t]+=red[t+o]; __syncthreads(); }
    float rstd = rsqrtf(red[0]*(1.f/CH) + 1e-5f);
    zr[t]     = d0*rstd*g[t]     + b[t];
    zr[t+256] = d1*rstd*g[t+256] + b[t+256];
}

// ---------------- prior reductions ----------------
__global__ void k_prior_reduce(const float* __restrict__ pri, const float* __restrict__ conn)
{
    int bp = blockIdx.x; int b = bp / CP;
    const float* p = pri + (long long)bp*CNN;
    const float* c = conn + (long long)b*CNN;
    float dot=0, sq=0, ab=0;
    for (int i = threadIdx.x; i < CNN; i += blockDim.x) {
        float pv = p[i];
        dot += pv*c[i]; sq += pv*pv; ab += fabsf(pv);
    }
    __shared__ float r1[256], r2[256], r3[256];
    int t=threadIdx.x; r1[t]=dot;r2[t]=sq;r3[t]=ab; __syncthreads();
    for(int o=128;o>0;o>>=1){ if(t<o){r1[t]+=r1[t+o];r2[t]+=r2[t+o];r3[t]+=r3[t+o];} __syncthreads(); }
    if(t==0){ g_dot[bp]=r1[0]; g_psq[bp]=r2[0]; g_pabs[bp]=r3[0]; }
}

__global__ void k_conn_sumsq(const float* __restrict__ conn)
{
    int b = blockIdx.x;
    const float* c = conn + (long long)b*CNN;
    float sq=0;
    for (int i = threadIdx.x; i < CNN; i += blockDim.x) { float v=c[i]; sq += v*v; }
    __shared__ float r[256];
    int t=threadIdx.x; r[t]=sq; __syncthreads();
    for(int o=128;o>0;o>>=1){ if(t<o) r[t]+=r[t+o]; __syncthreads(); }
    if(t==0) g_csq[b]=r[0];
}

__global__ void k_sw()
{
    if (threadIdx.x) return;
    int b = blockIdx.x;
    float cn = fmaxf(sqrtf(g_csq[b]), 1e-12f);
    float s[CP], mx=-1e30f;
    for (int p=0;p<CP;p++){
        float pn = fmaxf(sqrtf(g_psq[b*CP+p]), 1e-12f);
        s[p] = g_dot[b*CP+p]/(cn*pn);
        mx = fmaxf(mx, s[p]);
    }
    float sum=0;
    for (int p=0;p<CP;p++){ s[p]=expf(s[p]-mx); sum+=s[p]; }
    for (int p=0;p<CP;p++){
        g_sw[b*CP+p]=s[p]/sum;
        g_invmass[b*CP+p] = 1.f/g_pabs[b*CP+p];
    }
}

// ---------------- fused_nh[b,n,c] = sum_p sw[b,p]*pe[b,p,n,c] ----------------
__global__ void k_fused_nh()
{
    long long idx = (long long)blockIdx.x*blockDim.x + threadIdx.x;
    if (idx >= (long long)CBN*CH) return;
    int c = (int)(idx % CH);
    long long bn = idx / CH;
    int b = (int)(bn / CN), n = (int)(bn % CN);
    float acc=0;
    #pragma unroll
    for (int p=0;p<CP;p++)
        acc += g_sw[b*CP+p]*g_pe[((long long)(b*CP+p)*CN + n)*CH + c];
    g_fn[idx]=acc;
}

// ---------------- gbar two-stage: partials over 48-row chunks, then reduce ----------------
__global__ void k_gbar_part()
{
    int blk = blockIdx.x;           // CB*CP*8
    int bp = blk >> 3, ch = blk & 7;
    int c = threadIdx.x;
    int nlo = ch*48, nhi = nlo+48; if (nhi > CN) nhi = CN;
    float a0=0, a1=0;
    for (int n=nlo; n<nhi; n++){
        const float* r = g_h + ((long long)bp*CN+n)*CH;
        a0 += r[c]; a1 += r[c+256];
    }
    g_gpart[(long long)blk*CH + c]       = a0;
    g_gpart[(long long)blk*CH + c + 256] = a1;
}

__global__ void k_gbar_fin()
{
    int bp = blockIdx.x; int c = threadIdx.x;
    float a0=0, a1=0;
    #pragma unroll
    for (int ch=0; ch<8; ch++){
        const float* r = g_gpart + (long long)(bp*8+ch)*CH;
        a0 += r[c]; a1 += r[c+256];
    }
    g_gbar[bp*CH+c]     = a0*(1.f/CN);
    g_gbar[bp*CH+c+256] = a1*(1.f/CN);
}

// ---------------- tiny weight-gen MHA -> aw_, msum ----------------
__global__ void k_wg_attn(float* __restrict__ aw_out)
{
    int b = blockIdx.x;
    __shared__ float logit[CWGH*CP*CP];   // 36 floats
    int t = threadIdx.x;                  // 64 threads
    if (t < CWGH*CP*CP) {
        int h = t/(CP*CP); int i = (t/CP)%CP; int j = t%CP;
        const float* q = g_qkvwg + (long long)(b*CP+i)*3*CH + h*128;
        const float* k = g_qkvwg + (long long)(b*CP+j)*3*CH + CH + h*128;
        float d=0;
        for (int x=0;x<128;x++) d += q[x]*k[x];
        logit[t] = d*0.08838834764831845f;   // 1/sqrt(128)
    }
    __syncthreads();
    if (t==0) {
        float aw[CP]={0,0,0};
        for (int h=0;h<CWGH;h++) for (int i=0;i<CP;i++) {
            float mx=-1e30f;
            for (int j=0;j<CP;j++) mx=fmaxf(mx, logit[(h*CP+i)*CP+j]);
            float e[CP], s=0;
            for (int j=0;j<CP;j++){ e[j]=expf(logit[(h*CP+i)*CP+j]-mx); s+=e[j]; }
            for (int j=0;j<CP;j++) aw[j]+= e[j]/s;
        }
        for (int j=0;j<CP;j++) aw[j] *= (1.f/(CWGH*CP));
        float mx=-1e30f;
        for (int j=0;j<CP;j++) mx=fmaxf(mx, aw[j]);
        float s=0, e[CP];
        for (int j=0;j<CP;j++){ e[j]=expf((aw[j]-mx)*100.f); s+=e[j]; }  // temp 0.01
        float msum=0;
        for (int j=0;j<CP;j++){ float a=e[j]/s; aw_out[b*CP+j]=a; msum+=a; }
        g_msum[b]=msum;
    }
}

// ---------------- mask = tanh(a/2*msum + (1-a/2)*conn) ----------------
__global__ void k_mask(const float* __restrict__ conn, const float* __restrict__ alpha)
{
    long long idx = (long long)blockIdx.x*blockDim.x + threadIdx.x;
    if (idx >= (long long)CB*CNN) return;
    int b = (int)(idx / CNN);
    float a2 = alpha[0]*0.5f;
    g_mask[idx] = tanhf(a2*g_msum[b] + (1.f-a2)*conn[idx]);
}

// ---------------- scores: 1-D grid, 256 thr, 32x32 tile, k-chunk 16 ----------------
__global__ void k_scores()
{
    int blk = blockIdx.x;            // 256*144 blocks
    int bh = blk / 144;
    int r  = blk % 144;
    int b = bh >> 3, h = bh & 7;
    int i0 = (r / 12) * 32, j0 = (r % 12) * 32;
    __shared__ float Qs[32][17], Ks[32][17];
    int t = threadIdx.x;
    int lr = t >> 3;                 // 0..31
    int lc = (t & 7) * 2;            // 0..14
    int ti = t >> 4, tj = t & 15;
    float a00=0,a01=0,a10=0,a11=0;
    int gi_l = i0 + lr, gj_l = j0 + lr;
    for (int k0 = 0; k0 < CHD; k0 += 16) {
        #pragma unroll
        for (int u=0;u<2;u++){
            Qs[lr][lc+u] = (gi_l<CN)? g_qkv[(long long)(b*CN+gi_l)*3*CH + h*CHD + k0+lc+u] : 0.f;
            Ks[lr][lc+u] = (gj_l<CN)? g_qkv[(long long)(b*CN+gj_l)*3*CH + CH + h*CHD + k0+lc+u] : 0.f;
        }
        __syncthreads();
        #pragma unroll
        for (int x=0;x<16;x++){
            float q0=Qs[ti][x], q1=Qs[ti+16][x];
            float kv0=Ks[tj][x], kv1=Ks[tj+16][x];
            a00+=q0*kv0; a01+=q0*kv1; a10+=q1*kv0; a11+=q1*kv1;
        }
        __syncthreads();
    }
    float* srow = g_scores + (long long)bh*CNN;
    const float* mrow = g_mask + (long long)b*CNN;
    int i_[2] = {i0+ti, i0+ti+16};
    int j_[2] = {j0+tj, j0+tj+16};
    float av[2][2] = {{a00,a01},{a10,a11}};
    #pragma unroll
    for (int ii=0;ii<2;ii++){
        if (i_[ii] >= CN) continue;
        #pragma unroll
        for (int jj=0;jj<2;jj++){
            if (j_[jj] >= CN) continue;
            long long o = (long long)i_[ii]*CN + j_[jj];
            srow[o] = 0.125f*av[ii][jj]*(1.f + mrow[o]);
        }
    }
}

__global__ void k_softmax_rows(float* __restrict__ s, int cols)
{
    long long row = blockIdx.x;
    float* r = s + row*(long long)cols;
    __shared__ float red[128];
    int t = threadIdx.x;
    float mx = -1e30f;
    for (int c=t;c<cols;c+=128) mx = fmaxf(mx, r[c]);
    red[t]=mx; __syncthreads();
    for(int o=64;o>0;o>>=1){ if(t<o) red[t]=fmaxf(red[t],red[t+o]); __syncthreads(); }
    mx = red[0]; __syncthreads();
    float sum=0;
    for (int c=t;c<cols;c+=128){ float e=expf(r[c]-mx); r[c]=e; sum+=e; }
    red[t]=sum; __syncthreads();
    for(int o=64;o>0;o>>=1){ if(t<o) red[t]+=red[t+o]; __syncthreads(); }
    float inv = 1.f/red[0];
    for (int c=t;c<cols;c+=128) r[c]*=inv;
}

// ---------------- ctx = P @ V, 1-D grid, 256 thr, j-chunk 16 ----------------
__global__ void k_ctx()
{
    int blk = blockIdx.x;            // 32*8*12 = 3072 blocks
    int b = blk / 96;
    int rem = blk % 96;
    int h = rem / 12;
    int i0 = (rem % 12) * 32;
    int t = threadIdx.x;
    int tx = t & 63;                 // d
    int ty = t >> 6;                 // 0..3
    __shared__ float Ps[32][17], Vs[16][65];
    float acc[8]={};
    const float* srow = g_scores + (long long)(b*CNH+h)*CNN;
    int pr = t >> 3, pc = (t & 7) * 2;   // Ps loader
    int vr = t >> 4, vc = (t & 15) * 4;  // Vs loader
    for (int j0=0;j0<CN;j0+=16) {
        int gi = i0 + pr;
        #pragma unroll
        for (int u=0;u<2;u++){
            int gj = j0 + pc + u;
            Ps[pr][pc+u] = (gi<CN && gj<CN) ? srow[(long long)gi*CN+gj] : 0.f;
        }
        int gj = j0 + vr;
        #pragma unroll
        for (int u=0;u<4;u++)
            Vs[vr][vc+u] = (gj<CN) ? g_qkv[(long long)(b*CN+gj)*3*CH + 2*CH + h*CHD + vc+u] : 0.f;
        __syncthreads();
        #pragma unroll
        for (int jj=0;jj<16;jj++){
            float vv = Vs[jj][tx];
            #pragma unroll
            for (int ii=0;ii<8;ii++)
                acc[ii] += Ps[ty+4*ii][jj]*vv;
        }
        __syncthreads();
    }
    #pragma unroll
    for (int ii=0;ii<8;ii++){
        int gi = i0+ty+4*ii;
        if (gi<CN) g_ctx[(long long)(b*CN+gi)*CH + h*CHD + tx] = acc[ii];
    }
}

// ---------------- elementwise combines ----------------
__global__ void k_add3(const float* __restrict__ x)
{
    long long idx = (long long)blockIdx.x*blockDim.x + threadIdx.x;
    if (idx >= (long long)CBN*CH) return;
    g_attnout[idx] = x[idx] + g_ctx[idx] + g_fn[idx];
}

__global__ void k_final(float* __restrict__ outx, const float* __restrict__ dwp, int sidx)
{
    long long idx = (long long)blockIdx.x*blockDim.x + threadIdx.x;
    if (idx >= (long long)CBN*CH) return;
    float w = dwp[sidx];
    float f = g_ffnout[idx];
    float xn = g_attnout[idx] + f;
    outx[idx] = xn;
    float pv = w*f + (1.f-w)*xn;
    if (sidx == 0) g_proj0[idx] = pv; else g_proj1[idx] = pv;
}

__global__ void k_logsoftmax(int which)
{
    float* p = which ? g_proj1 : g_proj0;
    long long row = blockIdx.x;
    float* r = p + row*(long long)CH;
    __shared__ float red[256];
    int t = threadIdx.x;
    float a = r[t], b = r[t+256];
    red[t] = fmaxf(a,b); __syncthreads();
    for(int o=128;o>0;o>>=1){ if(t<o) red[t]=fmaxf(red[t],red[t+o]); __syncthreads(); }
    float mx = red[0]; __syncthreads();
    red[t] = expf(a-mx)+expf(b-mx); __syncthreads();
    for(int o=128;o>0;o>>=1){ if(t<o) red[t]+=red[t+o]; __syncthreads(); }
    float lse = logf(red[0]) + mx;
    r[t] = a - lse; r[t+256] = b - lse;
}

__global__ void k_zero_kl(){ g_kl[0]=0.0; g_kl[1]=0.0; }

__global__ void k_kl()
{
    long long tot = (long long)CBN*CH;
    double t1=0,t2=0;
    for (long long i = (long long)blockIdx.x*blockDim.x+threadIdx.x; i<tot;
         i += (long long)gridDim.x*blockDim.x){
        float lf=g_proj0[i], ls=g_proj1[i];
        t1 += (double)(expf(ls)*(ls-lf));
        t2 += (double)(expf(lf)*(lf-ls));
    }
    __shared__ double r1[256], r2[256];
    int t=threadIdx.x; r1[t]=t1; r2[t]=t2; __syncthreads();
    for(int o=128;o>0;o>>=1){ if(t<o){r1[t]+=r1[t+o];r2[t]+=r2[t+o];} __syncthreads(); }
    if(t==0){ atomicAdd(&g_kl[0], r1[0]); atomicAdd(&g_kl[1], r2[0]); }
}

__global__ void k_loss(float* __restrict__ out)
{
    out[0] = (float)(0.5*(g_kl[0]+g_kl[1])/(double)CBN);
}

// ---------------- host orchestration ----------------
// CRITICAL: __device__ symbols passed as kernel ARGUMENTS must be resolved via
// cudaGetSymbolAddress (host shadow address + GB300 ATS silently reads host RAM).
static float* sym_addr(const void* symbol)
{
    void* p = nullptr;
    cudaGetSymbolAddress(&p, symbol);
    return (float*)p;
}

extern "C" void kernel_launch(void* const* d_in, const int* in_sizes, int n_in,
                              void* d_out, int out_size)
{
    const float* x[2]    = {(const float*)d_in[0], (const float*)d_in[1]};
    const float* pri[2]  = {(const float*)d_in[2], (const float*)d_in[3]};
    const float* conn[2] = {(const float*)d_in[4], (const float*)d_in[5]};
    const float* dw      = (const float*)d_in[6];
    const float* wqkv[2] = {(const float*)d_in[7], (const float*)d_in[8]};
    const float* ln_g    = (const float*)d_in[9];
    const float* ln_b    = (const float*)d_in[10];
    const float* ffn_w1  = (const float*)d_in[11];
    const float* ffn_b1  = (const float*)d_in[12];
    const float* ffn_w2  = (const float*)d_in[13];
    const float* ffn_b2  = (const float*)d_in[14];
    const float* pw      = (const float*)d_in[15];
    const float* pb      = (const float*)d_in[16];
    const float* f1w     = (const float*)d_in[17];
    const float* f1b     = (const float*)d_in[18];
    const float* f2w     = (const float*)d_in[19];
    const float* f2b     = (const float*)d_in[20];
    const float* ipw     = (const float*)d_in[21];
    const float* ipb     = (const float*)d_in[22];
    const float* alpha   = (const float*)d_in[23];
    float* out = (float*)d_out;

    float* p_z       = sym_addr(g_z);
    float* p_qkv     = sym_addr(g_qkv);
    float* p_pe      = sym_addr(g_pe);
    float* p_h       = sym_addr(g_h);
    float* p_zc      = sym_addr(g_zc);
    float* p_scores  = sym_addr(g_scores);
    float* p_attnout = sym_addr(g_attnout);
    float* p_ffnh    = sym_addr(g_ffnh);
    float* p_ffnout  = sym_addr(g_ffnout);
    float* p_gbar    = sym_addr(g_gbar);
    float* p_tokens  = sym_addr(g_tokens);
    float* p_qkvwg   = sym_addr(g_qkvwg);
    float* p_invmass = sym_addr(g_invmass);

    const int MB_BN  = (CBN  + 127) / 128;   // 95
    const int MB_BPN = (CBPN + 127) / 128;   // 285

    k_zero_kl<<<1,1>>>();

    for (int s = 0; s < 2; s++) {
        // 1. pre-attention LN
        k_layernorm<<<CBN,256>>>(x[s], ln_g + s*CH, ln_b + s*CH, p_z);
        // 2. QKV = z @ wqkv  (Nc=1536 -> 12 n-blocks of 128)
        gemm_tc<<<12*MB_BN,256>>>(p_z, wqkv[s], nullptr, p_qkv,
            CBN, CH, 3*CH, 12, nullptr, 1, nullptr, 0, 0);
        // 3. prior similarity + mass
        k_prior_reduce<<<CB*CP,256>>>(pri[s], conn[s]);
        k_conn_sumsq<<<CB,256>>>(conn[s]);
        k_sw<<<CB,32>>>();
        // 4. pe = (pri/mass) @ pw + pb  (K=379 -> scalar staging path)
        gemm_tc<<<4*MB_BPN,256>>>(pri[s], pw, pb, p_pe,
            CBPN, CN, CH, 4, p_invmass, CN, nullptr, 0, 0);
        // 5. fused_nh
        k_fused_nh<<<(X_SZ+255)/256,256>>>();
        // 6. zc = z @ f1w[512:] + f1b
        gemm_tc<<<4*MB_BN,256>>>(p_z, f1w + CH*CH, f1b, p_zc,
            CBN, CH, CH, 4, nullptr, 1, nullptr, 0, 0);
        // 7. g = gelu(pe @ f1w[:512] + zc)
        gemm_tc<<<4*MB_BPN,256>>>(p_pe, f1w, nullptr, p_h,
            CBPN, CH, CH, 4, nullptr, 1, p_zc, 2, 1);
        // 8. gbar (two-stage) ; tokens ; qkv_wg
        k_gbar_part<<<CB*CP*8,256>>>();
        k_gbar_fin<<<CB*CP,256>>>();
        gemm_tc<<<4*1,256>>>(p_gbar, f2w, f2b, p_tokens,
            CB*CP, CH, CH, 4, nullptr, 1, nullptr, 0, 0);
        gemm_tc<<<12*1,256>>>(p_tokens, ipw, ipb, p_qkvwg,
            CB*CP, CH, 3*CH, 12, nullptr, 1, nullptr, 0, 0);
        // 9. tiny MHA -> aw_, msum ; mask
        k_wg_attn<<<CB,64>>>(out + (s ? AWSC_OFF : AWFC_OFF));
        k_mask<<<(CB*CNN+255)/256,256>>>(conn[s], alpha);
        // 10. attention
        k_scores<<<CB*CNH*144,256>>>();
        k_softmax_rows<<<CB*CNH*CN,128>>>(p_scores, CN);
        k_ctx<<<CB*CNH*12,256>>>();
        k_add3<<<(X_SZ+255)/256,256>>>(x[s]);
        // 11. FFN
        k_layernorm<<<CBN,256>>>(p_attnout, ln_g + (2+s)*CH, ln_b + (2+s)*CH, p_z);
        gemm_tc<<<16*MB_BN,256>>>(p_z, ffn_w1 + (long long)s*CH*4*CH,
            ffn_b1 + s*4*CH, p_ffnh, CBN, CH, 4*CH, 16, nullptr, 1, nullptr, 0, 1);
        gemm_tc<<<4*MB_BN,256>>>(p_ffnh, ffn_w2 + (long long)s*4*CH*CH,
            ffn_b2 + s*CH, p_ffnout, CBN, 4*CH, CH, 4, nullptr, 1, nullptr, 0, 0);
        // 12. residual + projection for distill
        k_final<<<(X_SZ+255)/256,256>>>(out + (long long)s*X_SZ, dw, s);
    }

    // distillation loss
    k_logsoftmax<<<CBN,256>>>(0);
    k_logsoftmax<<<CBN,256>>>(1);
    k_kl<<<1024,256>>>();
    k_loss<<<1,1>>>(out + LOSS_OFF);
}

// round 8
// speedup vs baseline: 2.6860x; 1.2470x over previous
#include <cuda_runtime.h>
#include <math.h>

// ---------------- problem constants ----------------
#define CB   32
#define CN   379
#define CH   512
#define CNH  8
#define CP   3
#define CWGH 4
#define CHD  64          // CH/CNH
#define CBN  (CB*CN)     // 12128
#define CBPN (CB*CP*CN)  // 36384
#define CNN  (CN*CN)     // 143641

#define X_SZ   (CBN*CH)          // 6209536
#define LOSS_OFF (2*X_SZ)
#define AWFC_OFF (LOSS_OFF+1)
#define AWSC_OFF (AWFC_OFF + CB*CP)

// gemm_tc dynamic smem: 2 x (128x36 + 32x136) words
#define GTC_SMEM ((2*128*36 + 2*32*136)*4)          // 71680 B
// k_attn dynamic smem: S 32x384 + Q 32x68 + T 32x68 words
#define ATT_SMEM ((32*384 + 32*68 + 32*68)*4)       // 66560 B

// ---------------- static scratch (zero-init by default) ----------------
static __device__ float g_z[CBN*CH];
static __device__ float g_qkv[CBN*3*CH];
static __device__ float g_pe[(long long)CBPN*CH];
static __device__ float g_h[(long long)CBPN*CH];
static __device__ float g_zc[CBN*CH];
static __device__ float g_fn[CBN*CH];
static __device__ float g_mask[(long long)CB*CNN];
static __device__ float g_ctx[CBN*CH];
static __device__ float g_attnout[CBN*CH];
static __device__ float g_ffnh[(long long)CBN*4*CH];
static __device__ float g_ffnout[CBN*CH];
static __device__ float g_proj0[CBN*CH];
static __device__ float g_proj1[CBN*CH];
static __device__ float g_gbar[CB*CP*CH];
static __device__ float g_gpart[CB*CP*8*CH];
static __device__ float g_tokens[CB*CP*CH];
static __device__ float g_qkvwg[CB*CP*3*CH];
static __device__ float g_dotp[CB*CP*8], g_psqp[CB*CP*8], g_pabsp[CB*CP*8];
static __device__ float g_csqp[CB*8];
static __device__ float g_sw[CB*CP], g_invmass[CB*CP], g_msum[CB];
static __device__ double g_kl[2];

__device__ __forceinline__ unsigned to_tf32(float v)
{
    unsigned r; asm("cvt.rna.tf32.f32 %0, %1;" : "=r"(r) : "f"(v)); return r;
}

// ---------------- tf32 tensor-core GEMM, cp.async double-buffered ----------------
// C = act(A@W + bias + res). A:(M,K) row-major fp32, W:(K,Nc) row-major fp32.
// Block tile 128x128, 256 threads = 8 warps (2m x 4n), warp tile 64x32,
// mma.sync m16n8k8 tf32 (raw fp32 bits -> HW truncation), k-chunk 32.
// Pipelined path needs K%32==0 and no rowScale; else synchronous fallback.
// resMode: 0 none, 1 res[gm*Nc+gn], 2 res[(b*CN+n)*Nc+gn] with gm=(b*CP+p)*CN+n.
__global__ void __launch_bounds__(256,2)
gemm_tc(const float* __restrict__ A, const float* __restrict__ W,
        const float* __restrict__ bias, float* __restrict__ C,
        int M, int K, int Nc, int gridNx,
        const float* __restrict__ rowScale, int rowScaleDiv,
        const float* __restrict__ res, int resMode, int act)
{
    extern __shared__ unsigned char s_raw[];
    unsigned (*As)[128][36] = (unsigned (*)[128][36])s_raw;
    unsigned (*Ws)[32][136] = (unsigned (*)[32][136])(s_raw + 2*128*36*4);

    const int t    = threadIdx.x;
    const int bx   = blockIdx.x % gridNx;
    const int by   = blockIdx.x / gridNx;
    const int m0   = by * 128;
    const int n0   = bx * 128;
    const int lane = t & 31, warp = t >> 5;
    const int wm   = warp >> 2;          // 0..1
    const int wn   = warp & 3;           // 0..3
    const int gid  = lane >> 2;          // 0..7
    const int tid4 = lane & 3;           // 0..3

    // A loader: warp = 4 rows x 128B contiguous; W loader: warp = 1 row x 512B
    const int ac4 = t & 7;               // float4 col 0..7
    const int ar0 = t >> 3;              // row 0..31, +32 per v
    const int wc4 = t & 31;              // float4 col 0..31
    const int wr0 = t >> 5;              // row 0..7, +8 per v

    float c[4][4][4];
    #pragma unroll
    for (int i=0;i<4;i++)
        #pragma unroll
        for (int j=0;j<4;j++)
            #pragma unroll
            for (int k=0;k<4;k++) c[i][j][k]=0.f;

    auto do_chunk = [&](const unsigned (*Ab)[36], const unsigned (*Wb)[136]) {
        #pragma unroll
        for (int k8 = 0; k8 < 32; k8 += 8) {
            unsigned a[4][4], b[4][2];
            #pragma unroll
            for (int ma = 0; ma < 4; ma++) {
                int rb = wm*64 + ma*16;
                a[ma][0] = Ab[rb + gid    ][k8 + tid4    ];
                a[ma][1] = Ab[rb + gid + 8][k8 + tid4    ];
                a[ma][2] = Ab[rb + gid    ][k8 + tid4 + 4];
                a[ma][3] = Ab[rb + gid + 8][k8 + tid4 + 4];
            }
            #pragma unroll
            for (int nb = 0; nb < 4; nb++) {
                int cn = wn*32 + nb*8 + gid;
                b[nb][0] = Wb[k8 + tid4    ][cn];
                b[nb][1] = Wb[k8 + tid4 + 4][cn];
            }
            #pragma unroll
            for (int ma = 0; ma < 4; ma++)
                #pragma unroll
                for (int nb = 0; nb < 4; nb++)
                    asm volatile(
                        "mma.sync.aligned.m16n8k8.row.col.f32.tf32.tf32.f32 "
                        "{%0,%1,%2,%3}, {%4,%5,%6,%7}, {%8,%9}, {%0,%1,%2,%3};"
                        : "+f"(c[ma][nb][0]), "+f"(c[ma][nb][1]),
                          "+f"(c[ma][nb][2]), "+f"(c[ma][nb][3])
                        : "r"(a[ma][0]), "r"(a[ma][1]), "r"(a[ma][2]), "r"(a[ma][3]),
                          "r"(b[nb][0]), "r"(b[nb][1]));
        }
    };

    const bool pipelined = ((K & 31) == 0) && (rowScale == nullptr);

    if (pipelined) {
        auto issue = [&](int kk, int buf) {
            #pragma unroll
            for (int v = 0; v < 4; v++) {            // A: 128x32
                int row = ar0 + 32*v;
                int gm  = m0 + row;
                const float* src = A + (long long)(gm < M ? gm : 0)*K + kk + ac4*4;
                unsigned dst = (unsigned)__cvta_generic_to_shared(&As[buf][row][ac4*4]);
                int sz = (gm < M) ? 16 : 0;
                asm volatile("cp.async.ca.shared.global [%0], [%1], 16, %2;"
                             :: "r"(dst), "l"(src), "r"(sz));
            }
            #pragma unroll
            for (int v = 0; v < 4; v++) {            // W: 32x128
                int row = wr0 + 8*v;
                int gk  = kk + row;
                const float* src = W + (long long)(gk < K ? gk : 0)*Nc + n0 + wc4*4;
                unsigned dst = (unsigned)__cvta_generic_to_shared(&Ws[buf][row][wc4*4]);
                int sz = (gk < K) ? 16 : 0;
                asm volatile("cp.async.ca.shared.global [%0], [%1], 16, %2;"
                             :: "r"(dst), "l"(src), "r"(sz));
            }
            asm volatile("cp.async.commit_group;");
        };
        int nb = K >> 5;
        issue(0, 0);
        int cur = 0;
        for (int cidx = 0; cidx < nb; cidx++) {
            asm volatile("cp.async.wait_group 0;" ::: "memory");
            __syncthreads();
            if (cidx + 1 < nb) issue((cidx+1) << 5, cur ^ 1);
            do_chunk(As[cur], Ws[cur]);
            __syncthreads();
            cur ^= 1;
        }
    } else {
        // synchronous scalar path (handles K%32!=0 and rowScale), buffer 0
        const int gmA = m0 + ar0;   // note: only 32 rows per v handled below
        for (int kk = 0; kk < K; kk += 32) {
            #pragma unroll
            for (int v = 0; v < 4; v++) {
                int row = ar0 + 32*v;
                int gm  = m0 + row;
                float sc = 1.f;
                if (rowScale && gm < M) sc = rowScale[gm / rowScaleDiv];
                const float* ap = A + (long long)gm*K;
                #pragma unroll
                for (int u = 0; u < 4; u++) {
                    int gk = kk + ac4*4 + u;
                    float val = (gm < M && gk < K) ? ap[gk]*sc : 0.f;
                    As[0][row][ac4*4 + u] = to_tf32(val);
                }
            }
            #pragma unroll
            for (int v = 0; v < 4; v++) {
                int row = wr0 + 8*v;
                int gk  = kk + row;
                #pragma unroll
                for (int u = 0; u < 4; u++) {
                    int gn = n0 + wc4*4 + u;
                    float val = (gk < K) ? W[(long long)gk*Nc + gn] : 0.f;
                    Ws[0][row][wc4*4 + u] = to_tf32(val);
                }
            }
            __syncthreads();
            do_chunk(As[0], Ws[0]);
            __syncthreads();
        }
        (void)gmA;
    }

    // ---- epilogue ----
    #pragma unroll
    for (int ma = 0; ma < 4; ma++) {
        #pragma unroll
        for (int rr = 0; rr < 2; rr++) {
            int gm = m0 + wm*64 + ma*16 + gid + rr*8;
            if (gm >= M) continue;
            long long resBase = 0;
            if (resMode == 1) resBase = (long long)gm * Nc;
            else if (resMode == 2) {
                int bb = gm / (CP * CN);
                int nn = gm % CN;
                resBase = ((long long)bb * CN + nn) * (long long)Nc;
            }
            #pragma unroll
            for (int nb = 0; nb < 4; nb++) {
                #pragma unroll
                for (int cc = 0; cc < 2; cc++) {
                    int gn = n0 + wn*32 + nb*8 + 2*tid4 + cc;
                    float v = c[ma][nb][rr*2 + cc];
                    if (bias) v += bias[gn];
                    if (resMode) v += res[resBase + gn];
                    if (act) v = 0.5f * v * (1.f + erff(v * 0.70710678118654752f));
                    C[(long long)gm * Nc + gn] = v;
                }
            }
        }
    }
}

// ---------------- fused attention: scores+mask+softmax+PV, one (b,h,32-row) block --------
__global__ void __launch_bounds__(256) k_attn()
{
    extern __shared__ unsigned char s_raw[];
    float (*S)[384]  = (float (*)[384])s_raw;
    float (*Qs)[68]  = (float (*)[68])(s_raw + 32*384*4);
    float (*Ts)[68]  = (float (*)[68])(s_raw + 32*384*4 + 32*68*4);

    int blk = blockIdx.x;            // CB*CNH*12
    int b = blk / 96;
    int rem = blk % 96;
    int h = rem / 12;
    int i0 = (rem % 12) * 32;
    int t = threadIdx.x;

    // load Q tile 32x64
    {
        int r = t >> 3, c0 = (t & 7) * 8;
        int gi = i0 + r;
        const float* src = g_qkv + ((long long)(b*CN + (gi < CN ? gi : 0)))*3*CH + h*CHD + c0;
        #pragma unroll
        for (int u = 0; u < 8; u++) Qs[r][c0+u] = (gi < CN) ? src[u] : 0.f;
    }

    // phase 1: S = Q K^T
    int ti = t >> 4, tj = t & 15;
    for (int j0 = 0; j0 < CN; j0 += 32) {
        __syncthreads();
        {
            int r = t >> 3, c0 = (t & 7) * 8;
            int gj = j0 + r;
            const float* src = g_qkv + ((long long)(b*CN + (gj < CN ? gj : 0)))*3*CH + CH + h*CHD + c0;
            #pragma unroll
            for (int u = 0; u < 8; u++) Ts[r][c0+u] = (gj < CN) ? src[u] : 0.f;
        }
        __syncthreads();
        float a00=0,a01=0,a10=0,a11=0;
        #pragma unroll
        for (int x = 0; x < 64; x++) {
            float q0 = Qs[ti][x],    q1 = Qs[ti+16][x];
            float k0 = Ts[tj][x],    k1 = Ts[tj+16][x];
            a00 += q0*k0; a01 += q0*k1; a10 += q1*k0; a11 += q1*k1;
        }
        S[ti   ][j0+tj   ] = a00;
        S[ti   ][j0+tj+16] = a01;
        S[ti+16][j0+tj   ] = a10;
        S[ti+16][j0+tj+16] = a11;
    }
    __syncthreads();

    // phase 2: mask + scale + row softmax (warp w owns rows 4w..4w+3)
    int warp = t >> 5, lane = t & 31;
    for (int rr = 0; rr < 4; rr++) {
        int i = warp*4 + rr;
        int gi = i0 + i;
        if (gi >= CN) continue;
        const float* mrow = g_mask + (long long)b*CNN + (long long)gi*CN;
        float mx = -1e30f;
        for (int jc = lane; jc < CN; jc += 32) {
            float v = 0.125f * S[i][jc] * (1.f + mrow[jc]);
            S[i][jc] = v;
            mx = fmaxf(mx, v);
        }
        #pragma unroll
        for (int o = 16; o > 0; o >>= 1) mx = fmaxf(mx, __shfl_xor_sync(~0u, mx, o));
        float sum = 0.f;
        for (int jc = lane; jc < CN; jc += 32) {
            float e = expf(S[i][jc] - mx);
            S[i][jc] = e;
            sum += e;
        }
        #pragma unroll
        for (int o = 16; o > 0; o >>= 1) sum += __shfl_xor_sync(~0u, sum, o);
        float inv = 1.f / sum;
        for (int jc = lane; jc < CN; jc += 32) S[i][jc] *= inv;
    }
    __syncthreads();

    // phase 3: ctx = P @ V
    int tx = t & 63, ty = t >> 6;
    float acc[8] = {};
    for (int j0 = 0; j0 < CN; j0 += 32) {
        {
            int r = t >> 3, c0 = (t & 7) * 8;
            int gj = j0 + r;
            const float* src = g_qkv + ((long long)(b*CN + (gj < CN ? gj : 0)))*3*CH + 2*CH + h*CHD + c0;
            #pragma unroll
            for (int u = 0; u < 8; u++) Ts[r][c0+u] = (gj < CN) ? src[u] : 0.f;
        }
        __syncthreads();
        #pragma unroll
        for (int jj = 0; jj < 32; jj++) {
            float vv = Ts[jj][tx];
            #pragma unroll
            for (int ii = 0; ii < 8; ii++)
                acc[ii] += S[ty + 4*ii][j0 + jj] * vv;
        }
        __syncthreads();
    }
    #pragma unroll
    for (int ii = 0; ii < 8; ii++) {
        int gi = i0 + ty + 4*ii;
        if (gi < CN) g_ctx[((long long)(b*CN + gi))*CH + h*CHD + tx] = acc[ii];
    }
}

// ---------------- layernorm ----------------
__global__ void k_layernorm(const float* __restrict__ x, const float* __restrict__ g,
                            const float* __restrict__ b, float* __restrict__ z)
{
    int row = blockIdx.x;
    const float* xr = x + (long long)row*CH;
    float* zr = z + (long long)row*CH;
    __shared__ float red[256];
    int t = threadIdx.x;
    float v0 = xr[t], v1 = xr[t+256];
    red[t] = v0+v1; __syncthreads();
    for (int o=128;o>0;o>>=1){ if(t<o) red[t]+=red[t+o]; __syncthreads(); }
    float mean = red[0]*(1.f/CH); __syncthreads();
    float d0=v0-mean, d1=v1-mean;
    red[t]=d0*d0+d1*d1; __syncthreads();
    for (int o=128;o>0;o>>=1){ if(t<o) red[t]+=red[t+o]; __syncthreads(); }
    float rstd = rsqrtf(red[0]*(1.f/CH) + 1e-5f);
    zr[t]     = d0*rstd*g[t]     + b[t];
    zr[t+256] = d1*rstd*g[t+256] + b[t+256];
}

// ---------------- prior reductions: two-stage partials ----------------
__global__ void k_prior_part(const float* __restrict__ pri, const float* __restrict__ conn)
{
    int blk = blockIdx.x;           // CB*CP*8
    int bp = blk >> 3, ch = blk & 7;
    int b = bp / CP;
    const int CHK = (CNN + 7) / 8;
    int lo = ch*CHK, hi = lo + CHK; if (hi > CNN) hi = CNN;
    const float* p = pri  + (long long)bp*CNN;
    const float* c = conn + (long long)b*CNN;
    float dot=0, sq=0, ab=0;
    for (int i = lo + threadIdx.x; i < hi; i += blockDim.x) {
        float pv = p[i];
        dot += pv*c[i]; sq += pv*pv; ab += fabsf(pv);
    }
    __shared__ float r1[256], r2[256], r3[256];
    int t=threadIdx.x; r1[t]=dot;r2[t]=sq;r3[t]=ab; __syncthreads();
    for(int o=128;o>0;o>>=1){ if(t<o){r1[t]+=r1[t+o];r2[t]+=r2[t+o];r3[t]+=r3[t+o];} __syncthreads(); }
    if(t==0){ g_dotp[blk]=r1[0]; g_psqp[blk]=r2[0]; g_pabsp[blk]=r3[0]; }
}

__global__ void k_conn_part(const float* __restrict__ conn)
{
    int blk = blockIdx.x;           // CB*8
    int b = blk >> 3, ch = blk & 7;
    const int CHK = (CNN + 7) / 8;
    int lo = ch*CHK, hi = lo + CHK; if (hi > CNN) hi = CNN;
    const float* c = conn + (long long)b*CNN;
    float sq=0;
    for (int i = lo + threadIdx.x; i < hi; i += blockDim.x) { float v=c[i]; sq += v*v; }
    __shared__ float r[256];
    int t=threadIdx.x; r[t]=sq; __syncthreads();
    for(int o=128;o>0;o>>=1){ if(t<o) r[t]+=r[t+o]; __syncthreads(); }
    if(t==0) g_csqp[blk]=r[0];
}

__global__ void k_sw()
{
    if (threadIdx.x) return;
    int b = blockIdx.x;
    float csq=0;
    #pragma unroll
    for (int u=0;u<8;u++) csq += g_csqp[b*8+u];
    float cn = fmaxf(sqrtf(csq), 1e-12f);
    float s[CP], mx=-1e30f;
    for (int p=0;p<CP;p++){
        int bp = b*CP+p;
        float dot=0, sq=0, ab=0;
        #pragma unroll
        for (int u=0;u<8;u++){ dot+=g_dotp[bp*8+u]; sq+=g_psqp[bp*8+u]; ab+=g_pabsp[bp*8+u]; }
        float pn = fmaxf(sqrtf(sq), 1e-12f);
        s[p] = dot/(cn*pn);
        mx = fmaxf(mx, s[p]);
        g_invmass[bp] = 1.f/ab;
    }
    float sum=0;
    for (int p=0;p<CP;p++){ s[p]=expf(s[p]-mx); sum+=s[p]; }
    for (int p=0;p<CP;p++) g_sw[b*CP+p]=s[p]/sum;
}

// ---------------- fused_nh[b,n,c] = sum_p sw[b,p]*pe[b,p,n,c] ----------------
__global__ void k_fused_nh()
{
    long long idx = (long long)blockIdx.x*blockDim.x + threadIdx.x;
    if (idx >= (long long)CBN*CH) return;
    int c = (int)(idx % CH);
    long long bn = idx / CH;
    int b = (int)(bn / CN), n = (int)(bn % CN);
    float acc=0;
    #pragma unroll
    for (int p=0;p<CP;p++)
        acc += g_sw[b*CP+p]*g_pe[((long long)(b*CP+p)*CN + n)*CH + c];
    g_fn[idx]=acc;
}

// ---------------- gbar two-stage ----------------
__global__ void k_gbar_part()
{
    int blk = blockIdx.x;           // CB*CP*8
    int bp = blk >> 3, ch = blk & 7;
    int c = threadIdx.x;
    int nlo = ch*48, nhi = nlo+48; if (nhi > CN) nhi = CN;
    float a0=0, a1=0;
    for (int n=nlo; n<nhi; n++){
        const float* r = g_h + ((long long)bp*CN+n)*CH;
        a0 += r[c]; a1 += r[c+256];
    }
    g_gpart[(long long)blk*CH + c]       = a0;
    g_gpart[(long long)blk*CH + c + 256] = a1;
}

__global__ void k_gbar_fin()
{
    int bp = blockIdx.x; int c = threadIdx.x;
    float a0=0, a1=0;
    #pragma unroll
    for (int ch=0; ch<8; ch++){
        const float* r = g_gpart + (long long)(bp*8+ch)*CH;
        a0 += r[c]; a1 += r[c+256];
    }
    g_gbar[bp*CH+c]     = a0*(1.f/CN);
    g_gbar[bp*CH+c+256] = a1*(1.f/CN);
}

// ---------------- tiny weight-gen MHA -> aw_, msum ----------------
__global__ void k_wg_attn(float* __restrict__ aw_out)
{
    int b = blockIdx.x;
    __shared__ float logit[CWGH*CP*CP];
    int t = threadIdx.x;                  // 64 threads
    if (t < CWGH*CP*CP) {
        int h = t/(CP*CP); int i = (t/CP)%CP; int j = t%CP;
        const float* q = g_qkvwg + (long long)(b*CP+i)*3*CH + h*128;
        const float* k = g_qkvwg + (long long)(b*CP+j)*3*CH + CH + h*128;
        float d=0;
        for (int x=0;x<128;x++) d += q[x]*k[x];
        logit[t] = d*0.08838834764831845f;   // 1/sqrt(128)
    }
    __syncthreads();
    if (t==0) {
        float aw[CP]={0,0,0};
        for (int h=0;h<CWGH;h++) for (int i=0;i<CP;i++) {
            float mx=-1e30f;
            for (int j=0;j<CP;j++) mx=fmaxf(mx, logit[(h*CP+i)*CP+j]);
            float e[CP], s=0;
            for (int j=0;j<CP;j++){ e[j]=expf(logit[(h*CP+i)*CP+j]-mx); s+=e[j]; }
            for (int j=0;j<CP;j++) aw[j]+= e[j]/s;
        }
        for (int j=0;j<CP;j++) aw[j] *= (1.f/(CWGH*CP));
        float mx=-1e30f;
        for (int j=0;j<CP;j++) mx=fmaxf(mx, aw[j]);
        float s=0, e[CP];
        for (int j=0;j<CP;j++){ e[j]=expf((aw[j]-mx)*100.f); s+=e[j]; }  // temp 0.01
        float msum=0;
        for (int j=0;j<CP;j++){ float a=e[j]/s; aw_out[b*CP+j]=a; msum+=a; }
        g_msum[b]=msum;
    }
}

// ---------------- mask = tanh(a/2*msum + (1-a/2)*conn) ----------------
__global__ void k_mask(const float* __restrict__ conn, const float* __restrict__ alpha)
{
    long long idx = (long long)blockIdx.x*blockDim.x + threadIdx.x;
    if (idx >= (long long)CB*CNN) return;
    int b = (int)(idx / CNN);
    float a2 = alpha[0]*0.5f;
    g_mask[idx] = tanhf(a2*g_msum[b] + (1.f-a2)*conn[idx]);
}

// ---------------- elementwise combines ----------------
__global__ void k_add3(const float* __restrict__ x)
{
    long long idx = (long long)blockIdx.x*blockDim.x + threadIdx.x;
    if (idx >= (long long)CBN*CH) return;
    g_attnout[idx] = x[idx] + g_ctx[idx] + g_fn[idx];
}

__global__ void k_final(float* __restrict__ outx, const float* __restrict__ dwp, int sidx)
{
    long long idx = (long long)blockIdx.x*blockDim.x + threadIdx.x;
    if (idx >= (long long)CBN*CH) return;
    float w = dwp[sidx];
    float f = g_ffnout[idx];
    float xn = g_attnout[idx] + f;
    outx[idx] = xn;
    float pv = w*f + (1.f-w)*xn;
    if (sidx == 0) g_proj0[idx] = pv; else g_proj1[idx] = pv;
}

__global__ void k_logsoftmax(int which)
{
    float* p = which ? g_proj1 : g_proj0;
    long long row = blockIdx.x;
    float* r = p + row*(long long)CH;
    __shared__ float red[256];
    int t = threadIdx.x;
    float a = r[t], b = r[t+256];
    red[t] = fmaxf(a,b); __syncthreads();
    for(int o=128;o>0;o>>=1){ if(t<o) red[t]=fmaxf(red[t],red[t+o]); __syncthreads(); }
    float mx = red[0]; __syncthreads();
    red[t] = expf(a-mx)+expf(b-mx); __syncthreads();
    for(int o=128;o>0;o>>=1){ if(t<o) red[t]+=red[t+o]; __syncthreads(); }
    float lse = logf(red[0]) + mx;
    r[t] = a - lse; r[t+256] = b - lse;
}

__global__ void k_zero_kl(){ g_kl[0]=0.0; g_kl[1]=0.0; }

__global__ void k_kl()
{
    long long tot = (long long)CBN*CH;
    double t1=0,t2=0;
    for (long long i = (long long)blockIdx.x*blockDim.x+threadIdx.x; i<tot;
         i += (long long)gridDim.x*blockDim.x){
        float lf=g_proj0[i], ls=g_proj1[i];
        t1 += (double)(expf(ls)*(ls-lf));
        t2 += (double)(expf(lf)*(lf-ls));
    }
    __shared__ double r1[256], r2[256];
    int t=threadIdx.x; r1[t]=t1; r2[t]=t2; __syncthreads();
    for(int o=128;o>0;o>>=1){ if(t<o){r1[t]+=r1[t+o];r2[t]+=r2[t+o];} __syncthreads(); }
    if(t==0){ atomicAdd(&g_kl[0], r1[0]); atomicAdd(&g_kl[1], r2[0]); }
}

__global__ void k_loss(float* __restrict__ out)
{
    out[0] = (float)(0.5*(g_kl[0]+g_kl[1])/(double)CBN);
}

// ---------------- host orchestration ----------------
// CRITICAL: __device__ symbols passed as kernel ARGUMENTS must be resolved via
// cudaGetSymbolAddress (host shadow address + GB300 ATS silently reads host RAM).
static float* sym_addr(const void* symbol)
{
    void* p = nullptr;
    cudaGetSymbolAddress(&p, symbol);
    return (float*)p;
}

extern "C" void kernel_launch(void* const* d_in, const int* in_sizes, int n_in,
                              void* d_out, int out_size)
{
    const float* x[2]    = {(const float*)d_in[0], (const float*)d_in[1]};
    const float* pri[2]  = {(const float*)d_in[2], (const float*)d_in[3]};
    const float* conn[2] = {(const float*)d_in[4], (const float*)d_in[5]};
    const float* dw      = (const float*)d_in[6];
    const float* wqkv[2] = {(const float*)d_in[7], (const float*)d_in[8]};
    const float* ln_g    = (const float*)d_in[9];
    const float* ln_b    = (const float*)d_in[10];
    const float* ffn_w1  = (const float*)d_in[11];
    const float* ffn_b1  = (const float*)d_in[12];
    const float* ffn_w2  = (const float*)d_in[13];
    const float* ffn_b2  = (const float*)d_in[14];
    const float* pw      = (const float*)d_in[15];
    const float* pb      = (const float*)d_in[16];
    const float* f1w     = (const float*)d_in[17];
    const float* f1b     = (const float*)d_in[18];
    const float* f2w     = (const float*)d_in[19];
    const float* f2b     = (const float*)d_in[20];
    const float* ipw     = (const float*)d_in[21];
    const float* ipb     = (const float*)d_in[22];
    const float* alpha   = (const float*)d_in[23];
    float* out = (float*)d_out;

    float* p_z       = sym_addr(g_z);
    float* p_qkv     = sym_addr(g_qkv);
    float* p_pe      = sym_addr(g_pe);
    float* p_h       = sym_addr(g_h);
    float* p_zc      = sym_addr(g_zc);
    float* p_attnout = sym_addr(g_attnout);
    float* p_ffnh    = sym_addr(g_ffnh);
    float* p_ffnout  = sym_addr(g_ffnout);
    float* p_gbar    = sym_addr(g_gbar);
    float* p_tokens  = sym_addr(g_tokens);
    float* p_qkvwg   = sym_addr(g_qkvwg);
    float* p_invmass = sym_addr(g_invmass);

    // opt-in to >48KB dynamic smem (idempotent)
    cudaFuncSetAttribute(gemm_tc, cudaFuncAttributeMaxDynamicSharedMemorySize, GTC_SMEM);
    cudaFuncSetAttribute(k_attn,  cudaFuncAttributeMaxDynamicSharedMemorySize, ATT_SMEM);

    const int MB_BN  = (CBN  + 127) / 128;   // 95
    const int MB_BPN = (CBPN + 127) / 128;   // 285

    k_zero_kl<<<1,1>>>();

    for (int s = 0; s < 2; s++) {
        // 1. pre-attention LN
        k_layernorm<<<CBN,256>>>(x[s], ln_g + s*CH, ln_b + s*CH, p_z);
        // 2. QKV = z @ wqkv
        gemm_tc<<<12*MB_BN,256,GTC_SMEM>>>(p_z, wqkv[s], nullptr, p_qkv,
            CBN, CH, 3*CH, 12, nullptr, 1, nullptr, 0, 0);
        // 3. prior similarity + mass (two-stage)
        k_prior_part<<<CB*CP*8,256>>>(pri[s], conn[s]);
        k_conn_part<<<CB*8,256>>>(conn[s]);
        k_sw<<<CB,32>>>();
        // 4. pe = (pri/mass) @ pw + pb  (K=379 + rowScale -> fallback path)
        gemm_tc<<<4*MB_BPN,256,GTC_SMEM>>>(pri[s], pw, pb, p_pe,
            CBPN, CN, CH, 4, p_invmass, CN, nullptr, 0, 0);
        // 5. fused_nh
        k_fused_nh<<<(X_SZ+255)/256,256>>>();
        // 6. zc = z @ f1w[512:] + f1b
        gemm_tc<<<4*MB_BN,256,GTC_SMEM>>>(p_z, f1w + CH*CH, f1b, p_zc,
            CBN, CH, CH, 4, nullptr, 1, nullptr, 0, 0);
        // 7. g = gelu(pe @ f1w[:512] + zc)
        gemm_tc<<<4*MB_BPN,256,GTC_SMEM>>>(p_pe, f1w, nullptr, p_h,
            CBPN, CH, CH, 4, nullptr, 1, p_zc, 2, 1);
        // 8. gbar (two-stage) ; tokens ; qkv_wg
        k_gbar_part<<<CB*CP*8,256>>>();
        k_gbar_fin<<<CB*CP,256>>>();
        gemm_tc<<<4*1,256,GTC_SMEM>>>(p_gbar, f2w, f2b, p_tokens,
            CB*CP, CH, CH, 4, nullptr, 1, nullptr, 0, 0);
        gemm_tc<<<12*1,256,GTC_SMEM>>>(p_tokens, ipw, ipb, p_qkvwg,
            CB*CP, CH, 3*CH, 12, nullptr, 1, nullptr, 0, 0);
        // 9. tiny MHA -> aw_, msum ; mask
        k_wg_attn<<<CB,64>>>(out + (s ? AWSC_OFF : AWFC_OFF));
        k_mask<<<(CB*CNN+255)/256,256>>>(conn[s], alpha);
        // 10. fused attention (scores+mask+softmax+PV)
        k_attn<<<CB*CNH*12,256,ATT_SMEM>>>();
        k_add3<<<(X_SZ+255)/256,256>>>(x[s]);
        // 11. FFN
        k_layernorm<<<CBN,256>>>(p_attnout, ln_g + (2+s)*CH, ln_b + (2+s)*CH, p_z);
        gemm_tc<<<16*MB_BN,256,GTC_SMEM>>>(p_z, ffn_w1 + (long long)s*CH*4*CH,
            ffn_b1 + s*4*CH, p_ffnh, CBN, CH, 4*CH, 16, nullptr, 1, nullptr, 0, 1);
        gemm_tc<<<4*MB_BN,256,GTC_SMEM>>>(p_ffnh, ffn_w2 + (long long)s*4*CH*CH,
            ffn_b2 + s*CH, p_ffnout, CBN, 4*CH, CH, 4, nullptr, 1, nullptr, 0, 0);
        // 12. residual + projection for distill
        k_final<<<(X_SZ+255)/256,256>>>(out + (long long)s*X_SZ, dw, s);
    }

    // distillation loss
    k_logsoftmax<<<CBN,256>>>(0);
    k_logsoftmax<<<CBN,256>>>(1);
    k_kl<<<1024,256>>>();
    k_loss<<<1,1>>>(out + LOSS_OFF);
}

// round 9
// speedup vs baseline: 2.9494x; 1.0981x over previous
#include <cuda_runtime.h>
#include <math.h>

// ---------------- problem constants ----------------
#define CB   32
#define CN   379
#define CH   512
#define CNH  8
#define CP   3
#define CWGH 4
#define CHD  64          // CH/CNH
#define CBN  (CB*CN)     // 12128
#define CBPN (CB*CP*CN)  // 36384
#define CNN  (CN*CN)     // 143641
#define KPAD 384         // pri K padded to multiple of 32

#define X_SZ   (CBN*CH)          // 6209536
#define LOSS_OFF (2*X_SZ)
#define AWFC_OFF (LOSS_OFF+1)
#define AWSC_OFF (AWFC_OFF + CB*CP)

// gemm_tc dynamic smem: 2 x (128x36 + 32x136) words
#define GTC_SMEM ((2*128*36 + 2*32*136)*4)          // 71680 B
// k_attn dynamic smem: S 32x384 + Q 32x68 + T 32x68 words
#define ATT_SMEM ((32*384 + 32*68 + 32*68)*4)       // 66560 B

// ---------------- static scratch (zero-init by default) ----------------
static __device__ float g_z[CBN*CH];
static __device__ float g_qkv[CBN*3*CH];
static __device__ float g_pe[(long long)CBPN*CH];
static __device__ float g_h[(long long)CBPN*CH];
static __device__ float g_zc[CBN*CH];
static __device__ float g_fn[CBN*CH];
static __device__ float g_mask[(long long)CB*CNN];
static __device__ float g_attnout[CBN*CH];
static __device__ float g_ffnh[(long long)CBN*4*CH];
static __device__ float g_proj0[CBN*CH];
static __device__ float g_proj1[CBN*CH];
static __device__ float g_pri_pad[(long long)CBPN*KPAD];
static __device__ float g_pw_pad[KPAD*CH];
static __device__ float g_gbar[CB*CP*CH];
static __device__ float g_gpart[CB*CP*8*CH];
static __device__ float g_tokens[CB*CP*CH];
static __device__ float g_qkvwg[CB*CP*3*CH];
static __device__ float g_dotp[CB*CP*8], g_psqp[CB*CP*8], g_pabsp[CB*CP*8];
static __device__ float g_csqp[CB*8];
static __device__ float g_sw[CB*CP], g_invmass[CB*CP], g_msum[CB];
static __device__ double g_kl[2];

__device__ __forceinline__ unsigned to_tf32(float v)
{
    unsigned r; asm("cvt.rna.tf32.f32 %0, %1;" : "=r"(r) : "f"(v)); return r;
}

// ---------------- tf32 tensor-core GEMM, cp.async double-buffered ----------------
// C = act(A@W + bias + res). A:(M,K) row-major fp32, W:(K,Nc) row-major fp32.
// Block tile 128x128, 256 threads = 8 warps (2m x 4n), warp tile 64x32,
// mma.sync m16n8k8 tf32 (raw fp32 bits -> HW truncation), k-chunk 32.
// Pipelined path needs K%32==0 and no rowScale; else synchronous fallback.
// resMode: 0 none, 1 res[gm*Nc+gn], 2 res[(b*CN+n)*Nc+gn] with gm=(b*CP+p)*CN+n,
//          3 = mode1 residual + dual write: C=xn, proj=xn - dwp[sidx]*res.
__global__ void __launch_bounds__(256,2)
gemm_tc(const float* __restrict__ A, const float* __restrict__ W,
        const float* __restrict__ bias, float* __restrict__ C,
        int M, int K, int Nc, int gridNx,
        const float* __restrict__ rowScale, int rowScaleDiv,
        const float* __restrict__ res, int resMode, int act,
        float* __restrict__ proj, const float* __restrict__ dwp, int sidx)
{
    extern __shared__ unsigned char s_raw[];
    unsigned (*As)[128][36] = (unsigned (*)[128][36])s_raw;
    unsigned (*Ws)[32][136] = (unsigned (*)[32][136])(s_raw + 2*128*36*4);

    const int t    = threadIdx.x;
    const int bx   = blockIdx.x % gridNx;
    const int by   = blockIdx.x / gridNx;
    const int m0   = by * 128;
    const int n0   = bx * 128;
    const int lane = t & 31, warp = t >> 5;
    const int wm   = warp >> 2;          // 0..1
    const int wn   = warp & 3;           // 0..3
    const int gid  = lane >> 2;          // 0..7
    const int tid4 = lane & 3;           // 0..3

    // A loader: warp = 4 rows x 128B contiguous; W loader: warp = 1 row x 512B
    const int ac4 = t & 7;               // float4 col 0..7
    const int ar0 = t >> 3;              // row 0..31, +32 per v
    const int wc4 = t & 31;              // float4 col 0..31
    const int wr0 = t >> 5;              // row 0..7, +8 per v

    const float wv = (resMode == 3) ? dwp[sidx] : 0.f;

    float c[4][4][4];
    #pragma unroll
    for (int i=0;i<4;i++)
        #pragma unroll
        for (int j=0;j<4;j++)
            #pragma unroll
            for (int k=0;k<4;k++) c[i][j][k]=0.f;

    auto do_chunk = [&](const unsigned (*Ab)[36], const unsigned (*Wb)[136]) {
        #pragma unroll
        for (int k8 = 0; k8 < 32; k8 += 8) {
            unsigned a[4][4], b[4][2];
            #pragma unroll
            for (int ma = 0; ma < 4; ma++) {
                int rb = wm*64 + ma*16;
                a[ma][0] = Ab[rb + gid    ][k8 + tid4    ];
                a[ma][1] = Ab[rb + gid + 8][k8 + tid4    ];
                a[ma][2] = Ab[rb + gid    ][k8 + tid4 + 4];
                a[ma][3] = Ab[rb + gid + 8][k8 + tid4 + 4];
            }
            #pragma unroll
            for (int nb = 0; nb < 4; nb++) {
                int cn = wn*32 + nb*8 + gid;
                b[nb][0] = Wb[k8 + tid4    ][cn];
                b[nb][1] = Wb[k8 + tid4 + 4][cn];
            }
            #pragma unroll
            for (int ma = 0; ma < 4; ma++)
                #pragma unroll
                for (int nb = 0; nb < 4; nb++)
                    asm volatile(
                        "mma.sync.aligned.m16n8k8.row.col.f32.tf32.tf32.f32 "
                        "{%0,%1,%2,%3}, {%4,%5,%6,%7}, {%8,%9}, {%0,%1,%2,%3};"
                        : "+f"(c[ma][nb][0]), "+f"(c[ma][nb][1]),
                          "+f"(c[ma][nb][2]), "+f"(c[ma][nb][3])
                        : "r"(a[ma][0]), "r"(a[ma][1]), "r"(a[ma][2]), "r"(a[ma][3]),
                          "r"(b[nb][0]), "r"(b[nb][1]));
        }
    };

    const bool pipelined = ((K & 31) == 0) && (rowScale == nullptr);

    if (pipelined) {
        auto issue = [&](int kk, int buf) {
            #pragma unroll
            for (int v = 0; v < 4; v++) {            // A: 128x32
                int row = ar0 + 32*v;
                int gm  = m0 + row;
                const float* src = A + (long long)(gm < M ? gm : 0)*K + kk + ac4*4;
                unsigned dst = (unsigned)__cvta_generic_to_shared(&As[buf][row][ac4*4]);
                int sz = (gm < M) ? 16 : 0;
                asm volatile("cp.async.ca.shared.global [%0], [%1], 16, %2;"
                             :: "r"(dst), "l"(src), "r"(sz));
            }
            #pragma unroll
            for (int v = 0; v < 4; v++) {            // W: 32x128
                int row = wr0 + 8*v;
                int gk  = kk + row;
                const float* src = W + (long long)(gk < K ? gk : 0)*Nc + n0 + wc4*4;
                unsigned dst = (unsigned)__cvta_generic_to_shared(&Ws[buf][row][wc4*4]);
                int sz = (gk < K) ? 16 : 0;
                asm volatile("cp.async.ca.shared.global [%0], [%1], 16, %2;"
                             :: "r"(dst), "l"(src), "r"(sz));
            }
            asm volatile("cp.async.commit_group;");
        };
        int nb = K >> 5;
        issue(0, 0);
        int cur = 0;
        for (int cidx = 0; cidx < nb; cidx++) {
            asm volatile("cp.async.wait_group 0;" ::: "memory");
            __syncthreads();
            if (cidx + 1 < nb) issue((cidx+1) << 5, cur ^ 1);
            do_chunk(As[cur], Ws[cur]);
            __syncthreads();
            cur ^= 1;
        }
    } else {
        // synchronous scalar path (K%32!=0 or rowScale)
        for (int kk = 0; kk < K; kk += 32) {
            #pragma unroll
            for (int v = 0; v < 4; v++) {
                int row = ar0 + 32*v;
                int gm  = m0 + row;
                float sc = 1.f;
                if (rowScale && gm < M) sc = rowScale[gm / rowScaleDiv];
                const float* ap = A + (long long)gm*K;
                #pragma unroll
                for (int u = 0; u < 4; u++) {
                    int gk = kk + ac4*4 + u;
                    float val = (gm < M && gk < K) ? ap[gk]*sc : 0.f;
                    As[0][row][ac4*4 + u] = to_tf32(val);
                }
            }
            #pragma unroll
            for (int v = 0; v < 4; v++) {
                int row = wr0 + 8*v;
                int gk  = kk + row;
                #pragma unroll
                for (int u = 0; u < 4; u++) {
                    int gn = n0 + wc4*4 + u;
                    float val = (gk < K) ? W[(long long)gk*Nc + gn] : 0.f;
                    Ws[0][row][wc4*4 + u] = to_tf32(val);
                }
            }
            __syncthreads();
            do_chunk(As[0], Ws[0]);
            __syncthreads();
        }
    }

    // ---- epilogue ----
    #pragma unroll
    for (int ma = 0; ma < 4; ma++) {
        #pragma unroll
        for (int rr = 0; rr < 2; rr++) {
            int gm = m0 + wm*64 + ma*16 + gid + rr*8;
            if (gm >= M) continue;
            long long resBase = 0;
            if (resMode == 1 || resMode == 3) resBase = (long long)gm * Nc;
            else if (resMode == 2) {
                int bb = gm / (CP * CN);
                int nn = gm % CN;
                resBase = ((long long)bb * CN + nn) * (long long)Nc;
            }
            #pragma unroll
            for (int nb = 0; nb < 4; nb++) {
                #pragma unroll
                for (int cc = 0; cc < 2; cc++) {
                    int gn = n0 + wn*32 + nb*8 + 2*tid4 + cc;
                    float v = c[ma][nb][rr*2 + cc];
                    if (bias) v += bias[gn];
                    if (resMode == 3) {
                        float r = res[resBase + gn];
                        float xn = v + r;
                        C[(long long)gm * Nc + gn] = xn;
                        proj[(long long)gm * Nc + gn] = xn - wv*r;
                        continue;
                    }
                    if (resMode) v += res[resBase + gn];
                    if (act) v = 0.5f * v * (1.f + erff(v * 0.70710678118654752f));
                    C[(long long)gm * Nc + gn] = v;
                }
            }
        }
    }
}

// ---------------- prescale priors: pri_pad = rna(pri * invmass), K padded to 384 ------
__global__ void k_prescale(const float* __restrict__ pri)
{
    long long idx = (long long)blockIdx.x*blockDim.x + threadIdx.x;
    if (idx >= (long long)CBPN*KPAD) return;
    int k = (int)(idx % KPAD);
    long long row = idx / KPAD;
    float v = 0.f;
    if (k < CN) v = pri[row*CN + k] * g_invmass[(int)(row / CN)];
    g_pri_pad[idx] = __uint_as_float(to_tf32(v));
}

__global__ void k_prep_pw(const float* __restrict__ pw)
{
    int idx = blockIdx.x*blockDim.x + threadIdx.x;
    if (idx >= KPAD*CH) return;
    int r = idx / CH, c = idx % CH;
    float v = (r < CN) ? pw[r*CH + c] : 0.f;
    g_pw_pad[idx] = __uint_as_float(to_tf32(v));
}

// ---------------- fused attention: scores+mask+softmax+PV+residual-add ----------------
__global__ void __launch_bounds__(256) k_attn(const float* __restrict__ x)
{
    extern __shared__ unsigned char s_raw[];
    float (*S)[384]  = (float (*)[384])s_raw;
    float (*Qs)[68]  = (float (*)[68])(s_raw + 32*384*4);
    float (*Ts)[68]  = (float (*)[68])(s_raw + 32*384*4 + 32*68*4);

    int blk = blockIdx.x;            // CB*CNH*12
    int b = blk / 96;
    int rem = blk % 96;
    int h = rem / 12;
    int i0 = (rem % 12) * 32;
    int t = threadIdx.x;

    // load Q tile 32x64
    {
        int r = t >> 3, c0 = (t & 7) * 8;
        int gi = i0 + r;
        const float* src = g_qkv + ((long long)(b*CN + (gi < CN ? gi : 0)))*3*CH + h*CHD + c0;
        #pragma unroll
        for (int u = 0; u < 8; u++) Qs[r][c0+u] = (gi < CN) ? src[u] : 0.f;
    }

    // phase 1: S = Q K^T
    int ti = t >> 4, tj = t & 15;
    for (int j0 = 0; j0 < CN; j0 += 32) {
        __syncthreads();
        {
            int r = t >> 3, c0 = (t & 7) * 8;
            int gj = j0 + r;
            const float* src = g_qkv + ((long long)(b*CN + (gj < CN ? gj : 0)))*3*CH + CH + h*CHD + c0;
            #pragma unroll
            for (int u = 0; u < 8; u++) Ts[r][c0+u] = (gj < CN) ? src[u] : 0.f;
        }
        __syncthreads();
        float a00=0,a01=0,a10=0,a11=0;
        #pragma unroll
        for (int xk = 0; xk < 64; xk++) {
            float q0 = Qs[ti][xk],    q1 = Qs[ti+16][xk];
            float k0 = Ts[tj][xk],    k1 = Ts[tj+16][xk];
            a00 += q0*k0; a01 += q0*k1; a10 += q1*k0; a11 += q1*k1;
        }
        S[ti   ][j0+tj   ] = a00;
        S[ti   ][j0+tj+16] = a01;
        S[ti+16][j0+tj   ] = a10;
        S[ti+16][j0+tj+16] = a11;
    }
    __syncthreads();

    // phase 2: mask + scale + row softmax (warp w owns rows 4w..4w+3)
    int warp = t >> 5, lane = t & 31;
    for (int rr = 0; rr < 4; rr++) {
        int i = warp*4 + rr;
        int gi = i0 + i;
        if (gi >= CN) continue;
        const float* mrow = g_mask + (long long)b*CNN + (long long)gi*CN;
        float mx = -1e30f;
        for (int jc = lane; jc < CN; jc += 32) {
            float v = 0.125f * S[i][jc] * (1.f + mrow[jc]);
            S[i][jc] = v;
            mx = fmaxf(mx, v);
        }
        #pragma unroll
        for (int o = 16; o > 0; o >>= 1) mx = fmaxf(mx, __shfl_xor_sync(~0u, mx, o));
        float sum = 0.f;
        for (int jc = lane; jc < CN; jc += 32) {
            float e = expf(S[i][jc] - mx);
            S[i][jc] = e;
            sum += e;
        }
        #pragma unroll
        for (int o = 16; o > 0; o >>= 1) sum += __shfl_xor_sync(~0u, sum, o);
        float inv = 1.f / sum;
        for (int jc = lane; jc < CN; jc += 32) S[i][jc] *= inv;
    }
    __syncthreads();

    // phase 3: ctx = P @ V, then attnout = x + ctx + fn (disjoint 64-col slice)
    int tx = t & 63, ty = t >> 6;
    float acc[8] = {};
    for (int j0 = 0; j0 < CN; j0 += 32) {
        {
            int r = t >> 3, c0 = (t & 7) * 8;
            int gj = j0 + r;
            const float* src = g_qkv + ((long long)(b*CN + (gj < CN ? gj : 0)))*3*CH + 2*CH + h*CHD + c0;
            #pragma unroll
            for (int u = 0; u < 8; u++) Ts[r][c0+u] = (gj < CN) ? src[u] : 0.f;
        }
        __syncthreads();
        #pragma unroll
        for (int jj = 0; jj < 32; jj++) {
            float vv = Ts[jj][tx];
            #pragma unroll
            for (int ii = 0; ii < 8; ii++)
                acc[ii] += S[ty + 4*ii][j0 + jj] * vv;
        }
        __syncthreads();
    }
    #pragma unroll
    for (int ii = 0; ii < 8; ii++) {
        int gi = i0 + ty + 4*ii;
        if (gi < CN) {
            long long o = ((long long)(b*CN + gi))*CH + h*CHD + tx;
            g_attnout[o] = x[o] + g_fn[o] + acc[ii];
        }
    }
}

// ---------------- layernorm ----------------
__global__ void k_layernorm(const float* __restrict__ x, const float* __restrict__ g,
                            const float* __restrict__ b, float* __restrict__ z)
{
    int row = blockIdx.x;
    const float* xr = x + (long long)row*CH;
    float* zr = z + (long long)row*CH;
    __shared__ float red[256];
    int t = threadIdx.x;
    float v0 = xr[t], v1 = xr[t+256];
    red[t] = v0+v1; __syncthreads();
    for (int o=128;o>0;o>>=1){ if(t<o) red[t]+=red[t+o]; __syncthreads(); }
    float mean = red[0]*(1.f/CH); __syncthreads();
    float d0=v0-mean, d1=v1-mean;
    red[t]=d0*d0+d1*d1; __syncthreads();
    for (int o=128;o>0;o>>=1){ if(t<o) red[t]+=red[t+o]; __syncthreads(); }
    float rstd = rsqrtf(red[0]*(1.f/CH) + 1e-5f);
    zr[t]     = d0*rstd*g[t]     + b[t];
    zr[t+256] = d1*rstd*g[t+256] + b[t+256];
}

// ---------------- prior reductions: two-stage partials ----------------
__global__ void k_prior_part(const float* __restrict__ pri, const float* __restrict__ conn)
{
    int blk = blockIdx.x;           // CB*CP*8
    int bp = blk >> 3, ch = blk & 7;
    int b = bp / CP;
    const int CHK = (CNN + 7) / 8;
    int lo = ch*CHK, hi = lo + CHK; if (hi > CNN) hi = CNN;
    const float* p = pri  + (long long)bp*CNN;
    const float* c = conn + (long long)b*CNN;
    float dot=0, sq=0, ab=0;
    for (int i = lo + threadIdx.x; i < hi; i += blockDim.x) {
        float pv = p[i];
        dot += pv*c[i]; sq += pv*pv; ab += fabsf(pv);
    }
    __shared__ float r1[256], r2[256], r3[256];
    int t=threadIdx.x; r1[t]=dot;r2[t]=sq;r3[t]=ab; __syncthreads();
    for(int o=128;o>0;o>>=1){ if(t<o){r1[t]+=r1[t+o];r2[t]+=r2[t+o];r3[t]+=r3[t+o];} __syncthreads(); }
    if(t==0){ g_dotp[blk]=r1[0]; g_psqp[blk]=r2[0]; g_pabsp[blk]=r3[0]; }
}

__global__ void k_conn_part(const float* __restrict__ conn)
{
    int blk = blockIdx.x;           // CB*8
    int b = blk >> 3, ch = blk & 7;
    const int CHK = (CNN + 7) / 8;
    int lo = ch*CHK, hi = lo + CHK; if (hi > CNN) hi = CNN;
    const float* c = conn + (long long)b*CNN;
    float sq=0;
    for (int i = lo + threadIdx.x; i < hi; i += blockDim.x) { float v=c[i]; sq += v*v; }
    __shared__ float r[256];
    int t=threadIdx.x; r[t]=sq; __syncthreads();
    for(int o=128;o>0;o>>=1){ if(t<o) r[t]+=r[t+o]; __syncthreads(); }
    if(t==0) g_csqp[blk]=r[0];
}

__global__ void k_sw()
{
    if (threadIdx.x) return;
    int b = blockIdx.x;
    float csq=0;
    #pragma unroll
    for (int u=0;u<8;u++) csq += g_csqp[b*8+u];
    float cn = fmaxf(sqrtf(csq), 1e-12f);
    float s[CP], mx=-1e30f;
    for (int p=0;p<CP;p++){
        int bp = b*CP+p;
        float dot=0, sq=0, ab=0;
        #pragma unroll
        for (int u=0;u<8;u++){ dot+=g_dotp[bp*8+u]; sq+=g_psqp[bp*8+u]; ab+=g_pabsp[bp*8+u]; }
        float pn = fmaxf(sqrtf(sq), 1e-12f);
        s[p] = dot/(cn*pn);
        mx = fmaxf(mx, s[p]);
        g_invmass[bp] = 1.f/ab;
    }
    float sum=0;
    for (int p=0;p<CP;p++){ s[p]=expf(s[p]-mx); sum+=s[p]; }
    for (int p=0;p<CP;p++) g_sw[b*CP+p]=s[p]/sum;
}

// ---------------- fused_nh[b,n,c] = sum_p sw[b,p]*pe[b,p,n,c] ----------------
__global__ void k_fused_nh()
{
    long long idx = (long long)blockIdx.x*blockDim.x + threadIdx.x;
    if (idx >= (long long)CBN*CH) return;
    int c = (int)(idx % CH);
    long long bn = idx / CH;
    int b = (int)(bn / CN), n = (int)(bn % CN);
    float acc=0;
    #pragma unroll
    for (int p=0;p<CP;p++)
        acc += g_sw[b*CP+p]*g_pe[((long long)(b*CP+p)*CN + n)*CH + c];
    g_fn[idx]=acc;
}

// ---------------- gbar two-stage ----------------
__global__ void k_gbar_part()
{
    int blk = blockIdx.x;           // CB*CP*8
    int bp = blk >> 3, ch = blk & 7;
    int c = threadIdx.x;
    int nlo = ch*48, nhi = nlo+48; if (nhi > CN) nhi = CN;
    float a0=0, a1=0;
    for (int n=nlo; n<nhi; n++){
        const float* r = g_h + ((long long)bp*CN+n)*CH;
        a0 += r[c]; a1 += r[c+256];
    }
    g_gpart[(long long)blk*CH + c]       = a0;
    g_gpart[(long long)blk*CH + c + 256] = a1;
}

__global__ void k_gbar_fin()
{
    int bp = blockIdx.x; int c = threadIdx.x;
    float a0=0, a1=0;
    #pragma unroll
    for (int ch=0; ch<8; ch++){
        const float* r = g_gpart + (long long)(bp*8+ch)*CH;
        a0 += r[c]; a1 += r[c+256];
    }
    g_gbar[bp*CH+c]     = a0*(1.f/CN);
    g_gbar[bp*CH+c+256] = a1*(1.f/CN);
}

// ---------------- tiny weight-gen MHA -> aw_, msum ----------------
__global__ void k_wg_attn(float* __restrict__ aw_out)
{
    int b = blockIdx.x;
    __shared__ float logit[CWGH*CP*CP];
    int t = threadIdx.x;                  // 64 threads
    if (t < CWGH*CP*CP) {
        int h = t/(CP*CP); int i = (t/CP)%CP; int j = t%CP;
        const float* q = g_qkvwg + (long long)(b*CP+i)*3*CH + h*128;
        const float* k = g_qkvwg + (long long)(b*CP+j)*3*CH + CH + h*128;
        float d=0;
        for (int x=0;x<128;x++) d += q[x]*k[x];
        logit[t] = d*0.08838834764831845f;   // 1/sqrt(128)
    }
    __syncthreads();
    if (t==0) {
        float aw[CP]={0,0,0};
        for (int h=0;h<CWGH;h++) for (int i=0;i<CP;i++) {
            float mx=-1e30f;
            for (int j=0;j<CP;j++) mx=fmaxf(mx, logit[(h*CP+i)*CP+j]);
            float e[CP], s=0;
            for (int j=0;j<CP;j++){ e[j]=expf(logit[(h*CP+i)*CP+j]-mx); s+=e[j]; }
            for (int j=0;j<CP;j++) aw[j]+= e[j]/s;
        }
        for (int j=0;j<CP;j++) aw[j] *= (1.f/(CWGH*CP));
        float mx=-1e30f;
        for (int j=0;j<CP;j++) mx=fmaxf(mx, aw[j]);
        float s=0, e[CP];
        for (int j=0;j<CP;j++){ e[j]=expf((aw[j]-mx)*100.f); s+=e[j]; }  // temp 0.01
        float msum=0;
        for (int j=0;j<CP;j++){ float a=e[j]/s; aw_out[b*CP+j]=a; msum+=a; }
        g_msum[b]=msum;
    }
}

// ---------------- mask = tanh(a/2*msum + (1-a/2)*conn) ----------------
__global__ void k_mask(const float* __restrict__ conn, const float* __restrict__ alpha)
{
    long long idx = (long long)blockIdx.x*blockDim.x + threadIdx.x;
    if (idx >= (long long)CB*CNN) return;
    int b = (int)(idx / CNN);
    float a2 = alpha[0]*0.5f;
    g_mask[idx] = tanhf(a2*g_msum[b] + (1.f-a2)*conn[idx]);
}

__global__ void k_logsoftmax(int which)
{
    float* p = which ? g_proj1 : g_proj0;
    long long row = blockIdx.x;
    float* r = p + row*(long long)CH;
    __shared__ float red[256];
    int t = threadIdx.x;
    float a = r[t], b = r[t+256];
    red[t] = fmaxf(a,b); __syncthreads();
    for(int o=128;o>0;o>>=1){ if(t<o) red[t]=fmaxf(red[t],red[t+o]); __syncthreads(); }
    float mx = red[0]; __syncthreads();
    red[t] = expf(a-mx)+expf(b-mx); __syncthreads();
    for(int o=128;o>0;o>>=1){ if(t<o) red[t]+=red[t+o]; __syncthreads(); }
    float lse = logf(red[0]) + mx;
    r[t] = a - lse; r[t+256] = b - lse;
}

__global__ void k_zero_kl(){ g_kl[0]=0.0; g_kl[1]=0.0; }

__global__ void k_kl()
{
    long long tot = (long long)CBN*CH;
    double t1=0,t2=0;
    for (long long i = (long long)blockIdx.x*blockDim.x+threadIdx.x; i<tot;
         i += (long long)gridDim.x*blockDim.x){
        float lf=g_proj0[i], ls=g_proj1[i];
        t1 += (double)(expf(ls)*(ls-lf));
        t2 += (double)(expf(lf)*(lf-ls));
    }
    __shared__ double r1[256], r2[256];
    int t=threadIdx.x; r1[t]=t1; r2[t]=t2; __syncthreads();
    for(int o=128;o>0;o>>=1){ if(t<o){r1[t]+=r1[t+o];r2[t]+=r2[t+o];} __syncthreads(); }
    if(t==0){ atomicAdd(&g_kl[0], r1[0]); atomicAdd(&g_kl[1], r2[0]); }
}

__global__ void k_loss(float* __restrict__ out)
{
    out[0] = (float)(0.5*(g_kl[0]+g_kl[1])/(double)CBN);
}

// ---------------- host orchestration ----------------
// CRITICAL: __device__ symbols passed as kernel ARGUMENTS must be resolved via
// cudaGetSymbolAddress (host shadow address + GB300 ATS silently reads host RAM).
static float* sym_addr(const void* symbol)
{
    void* p = nullptr;
    cudaGetSymbolAddress(&p, symbol);
    return (float*)p;
}

extern "C" void kernel_launch(void* const* d_in, const int* in_sizes, int n_in,
                              void* d_out, int out_size)
{
    const float* x[2]    = {(const float*)d_in[0], (const float*)d_in[1]};
    const float* pri[2]  = {(const float*)d_in[2], (const float*)d_in[3]};
    const float* conn[2] = {(const float*)d_in[4], (const float*)d_in[5]};
    const float* dw      = (const float*)d_in[6];
    const float* wqkv[2] = {(const float*)d_in[7], (const float*)d_in[8]};
    const float* ln_g    = (const float*)d_in[9];
    const float* ln_b    = (const float*)d_in[10];
    const float* ffn_w1  = (const float*)d_in[11];
    const float* ffn_b1  = (const float*)d_in[12];
    const float* ffn_w2  = (const float*)d_in[13];
    const float* ffn_b2  = (const float*)d_in[14];
    const float* pw      = (const float*)d_in[15];
    const float* pb      = (const float*)d_in[16];
    const float* f1w     = (const float*)d_in[17];
    const float* f1b     = (const float*)d_in[18];
    const float* f2w     = (const float*)d_in[19];
    const float* f2b     = (const float*)d_in[20];
    const float* ipw     = (const float*)d_in[21];
    const float* ipb     = (const float*)d_in[22];
    const float* alpha   = (const float*)d_in[23];
    float* out = (float*)d_out;

    float* p_z       = sym_addr(g_z);
    float* p_qkv     = sym_addr(g_qkv);
    float* p_pe      = sym_addr(g_pe);
    float* p_h       = sym_addr(g_h);
    float* p_zc      = sym_addr(g_zc);
    float* p_attnout = sym_addr(g_attnout);
    float* p_ffnh    = sym_addr(g_ffnh);
    float* p_gbar    = sym_addr(g_gbar);
    float* p_tokens  = sym_addr(g_tokens);
    float* p_qkvwg   = sym_addr(g_qkvwg);
    float* p_proj0   = sym_addr(g_proj0);
    float* p_proj1   = sym_addr(g_proj1);
    float* p_pri_pad = sym_addr(g_pri_pad);
    float* p_pw_pad  = sym_addr(g_pw_pad);

    cudaFuncSetAttribute(gemm_tc, cudaFuncAttributeMaxDynamicSharedMemorySize, GTC_SMEM);
    cudaFuncSetAttribute(k_attn,  cudaFuncAttributeMaxDynamicSharedMemorySize, ATT_SMEM);

    const int MB_BN  = (CBN  + 127) / 128;   // 95
    const int MB_BPN = (CBPN + 127) / 128;   // 285

    k_zero_kl<<<1,1>>>();
    k_prep_pw<<<(KPAD*CH+255)/256,256>>>(pw);

    for (int s = 0; s < 2; s++) {
        // 1. pre-attention LN
        k_layernorm<<<CBN,256>>>(x[s], ln_g + s*CH, ln_b + s*CH, p_z);
        // 2. QKV = z @ wqkv
        gemm_tc<<<12*MB_BN,256,GTC_SMEM>>>(p_z, wqkv[s], nullptr, p_qkv,
            CBN, CH, 3*CH, 12, nullptr, 1, nullptr, 0, 0, nullptr, nullptr, 0);
        // 3. prior similarity + mass (two-stage) -> invmass
        k_prior_part<<<CB*CP*8,256>>>(pri[s], conn[s]);
        k_conn_part<<<CB*8,256>>>(conn[s]);
        k_sw<<<CB,32>>>();
        // 4. prescale priors (x invmass, pad K->384, rna) then PIPELINED pe GEMM
        k_prescale<<<(int)(((long long)CBPN*KPAD+255)/256),256>>>(pri[s]);
        gemm_tc<<<4*MB_BPN,256,GTC_SMEM>>>(p_pri_pad, p_pw_pad, pb, p_pe,
            CBPN, KPAD, CH, 4, nullptr, 1, nullptr, 0, 0, nullptr, nullptr, 0);
        // 5. fused_nh
        k_fused_nh<<<(X_SZ+255)/256,256>>>();
        // 6. zc = z @ f1w[512:] + f1b
        gemm_tc<<<4*MB_BN,256,GTC_SMEM>>>(p_z, f1w + CH*CH, f1b, p_zc,
            CBN, CH, CH, 4, nullptr, 1, nullptr, 0, 0, nullptr, nullptr, 0);
        // 7. g = gelu(pe @ f1w[:512] + zc)
        gemm_tc<<<4*MB_BPN,256,GTC_SMEM>>>(p_pe, f1w, nullptr, p_h,
            CBPN, CH, CH, 4, nullptr, 1, p_zc, 2, 1, nullptr, nullptr, 0);
        // 8. gbar (two-stage) ; tokens ; qkv_wg
        k_gbar_part<<<CB*CP*8,256>>>();
        k_gbar_fin<<<CB*CP,256>>>();
        gemm_tc<<<4*1,256,GTC_SMEM>>>(p_gbar, f2w, f2b, p_tokens,
            CB*CP, CH, CH, 4, nullptr, 1, nullptr, 0, 0, nullptr, nullptr, 0);
        gemm_tc<<<12*1,256,GTC_SMEM>>>(p_tokens, ipw, ipb, p_qkvwg,
            CB*CP, CH, 3*CH, 12, nullptr, 1, nullptr, 0, 0, nullptr, nullptr, 0);
        // 9. tiny MHA -> aw_, msum ; mask
        k_wg_attn<<<CB,64>>>(out + (s ? AWSC_OFF : AWFC_OFF));
        k_mask<<<(CB*CNN+255)/256,256>>>(conn[s], alpha);
        // 10. fused attention (scores+mask+softmax+PV + residual add3)
        k_attn<<<CB*CNH*12,256,ATT_SMEM>>>(x[s]);
        // 11. FFN; ffn2 epilogue writes x_new to out AND proj (resMode 3)
        k_layernorm<<<CBN,256>>>(p_attnout, ln_g + (2+s)*CH, ln_b + (2+s)*CH, p_z);
        gemm_tc<<<16*MB_BN,256,GTC_SMEM>>>(p_z, ffn_w1 + (long long)s*CH*4*CH,
            ffn_b1 + s*4*CH, p_ffnh, CBN, CH, 4*CH, 16, nullptr, 1, nullptr, 0, 1,
            nullptr, nullptr, 0);
        gemm_tc<<<4*MB_BN,256,GTC_SMEM>>>(p_ffnh, ffn_w2 + (long long)s*4*CH*CH,
            ffn_b2 + s*CH, out + (long long)s*X_SZ, CBN, 4*CH, CH, 4, nullptr, 1,
            p_attnout, 3, 0, (s ? p_proj1 : p_proj0), dw, s);
    }

    // distillation loss
    k_logsoftmax<<<CBN,256>>>(0);
    k_logsoftmax<<<CBN,256>>>(1);
    k_kl<<<1024,256>>>();
    k_loss<<<1,1>>>(out + LOSS_OFF);
}